// round 1
// baseline (speedup 1.0000x reference)
#include <cuda_runtime.h>
#include <cstddef>

#define N_NODES 100000
#define N_EDGES 600000
#define FEAT    128
#define NREL    5

// ---- device-global scratch (allocation-free contract) ----
__device__ float g_all_h[(size_t)NREL * N_NODES * FEAT];   // 256 MB: h @ W_r for r=0..4
__device__ int   g_count[N_NODES];
__device__ int   g_cursor[N_NODES];
__device__ int   g_start[N_NODES + 1];
__device__ int   g_edge_idx[N_EDGES];

// ============================================================================
// Phase A: 6 GEMMs [N_NODES x 128] @ [128 x 128].
//   blockIdx.y = r: r<5 -> g_all_h slab r; r==5 -> W_0, written to d_out
//   128x128 output tile, K-chunks of 32, 256 threads, 8x8 microtile/thread.
// ============================================================================
__global__ __launch_bounds__(256) void gemm_kernel(
    const float* __restrict__ h, const float* __restrict__ weight,
    const float* __restrict__ W0, float* __restrict__ out)
{
    const int r  = blockIdx.y;
    const int m0 = blockIdx.x * 128;
    const float* __restrict__ W =
        (r == NREL) ? W0 : (weight + (size_t)r * FEAT * FEAT);
    float* __restrict__ C =
        (r == NREL) ? out : (g_all_h + (size_t)r * N_NODES * FEAT);

    __shared__ float As[128][33];   // [m][k], +1 pad
    __shared__ float Bs[32][132];   // [k][o], +4 pad (keeps float4 alignment)

    const int tid = threadIdx.x;
    const int tx  = tid & 15;   // output-col group
    const int ty  = tid >> 4;   // output-row group

    float acc[8][8];
    #pragma unroll
    for (int i = 0; i < 8; i++)
        #pragma unroll
        for (int j = 0; j < 8; j++) acc[i][j] = 0.f;

    for (int k0 = 0; k0 < FEAT; k0 += 32) {
        // -- load A tile: 128 rows x 32 k-cols (float4 global loads) --
        {
            const int c  = (tid & 7) * 4;
            const int r0 = tid >> 3;
            #pragma unroll
            for (int p = 0; p < 4; p++) {
                const int m  = r0 + p * 32;
                const int gm = m0 + m;
                float4 v = make_float4(0.f, 0.f, 0.f, 0.f);
                if (gm < N_NODES)
                    v = *reinterpret_cast<const float4*>(
                        h + (size_t)gm * FEAT + k0 + c);
                As[m][c + 0] = v.x; As[m][c + 1] = v.y;
                As[m][c + 2] = v.z; As[m][c + 3] = v.w;
            }
        }
        // -- load B tile: 32 k-rows x 128 out-cols --
        {
            const int o   = (tid & 31) * 4;
            const int kk0 = tid >> 5;
            #pragma unroll
            for (int p = 0; p < 4; p++) {
                const int k = kk0 + p * 8;
                float4 v = *reinterpret_cast<const float4*>(
                    W + (size_t)(k0 + k) * FEAT + o);
                *reinterpret_cast<float4*>(&Bs[k][o]) = v;
            }
        }
        __syncthreads();

        #pragma unroll
        for (int kk = 0; kk < 32; kk++) {
            float a[8], b[8];
            #pragma unroll
            for (int i = 0; i < 8; i++) a[i] = As[ty * 8 + i][kk];
            float4 b0 = *reinterpret_cast<const float4*>(&Bs[kk][tx * 8]);
            float4 b1 = *reinterpret_cast<const float4*>(&Bs[kk][tx * 8 + 4]);
            b[0] = b0.x; b[1] = b0.y; b[2] = b0.z; b[3] = b0.w;
            b[4] = b1.x; b[5] = b1.y; b[6] = b1.z; b[7] = b1.w;
            #pragma unroll
            for (int i = 0; i < 8; i++)
                #pragma unroll
                for (int j = 0; j < 8; j++)
                    acc[i][j] = fmaf(a[i], b[j], acc[i][j]);
        }
        __syncthreads();
    }

    #pragma unroll
    for (int i = 0; i < 8; i++) {
        const int gm = m0 + ty * 8 + i;
        if (gm < N_NODES) {
            float* p = C + (size_t)gm * FEAT + tx * 8;
            *reinterpret_cast<float4*>(p) =
                make_float4(acc[i][0], acc[i][1], acc[i][2], acc[i][3]);
            *reinterpret_cast<float4*>(p + 4) =
                make_float4(acc[i][4], acc[i][5], acc[i][6], acc[i][7]);
        }
    }
}

// ============================================================================
// Phase B prep: build CSR by dst (avoids 77M float atomics in the reduce)
// ============================================================================
__global__ void zero_kernel() {
    const int i = blockIdx.x * blockDim.x + threadIdx.x;
    if (i < N_NODES) { g_count[i] = 0; g_cursor[i] = 0; }
}

__global__ void hist_kernel(const int* __restrict__ dst) {
    const int e = blockIdx.x * blockDim.x + threadIdx.x;
    if (e < N_EDGES) atomicAdd(&g_count[dst[e]], 1);
}

__global__ __launch_bounds__(1024) void scan_kernel() {
    __shared__ int sums[1024];
    const int t = threadIdx.x;
    const int chunk = (N_NODES + 1023) / 1024;
    const int lo = t * chunk;
    const int hi = min(N_NODES, lo + chunk);
    int s = 0;
    for (int i = lo; i < hi; i++) s += g_count[i];
    sums[t] = s;
    __syncthreads();
    for (int off = 1; off < 1024; off <<= 1) {
        int x = (t >= off) ? sums[t - off] : 0;
        __syncthreads();
        sums[t] += x;
        __syncthreads();
    }
    int run = sums[t] - s;  // exclusive prefix of this thread's chunk
    for (int i = lo; i < hi; i++) { g_start[i] = run; run += g_count[i]; }
    if (t == 1023) g_start[N_NODES] = sums[1023];
}

__global__ void scatter_kernel(const int* __restrict__ dst) {
    const int e = blockIdx.x * blockDim.x + threadIdx.x;
    if (e < N_EDGES) {
        const int d = dst[e];
        const int pos = g_start[d] + atomicAdd(&g_cursor[d], 1);
        g_edge_idx[pos] = e;
    }
}

// ============================================================================
// Phase B: one warp per dst node. Gather all_h[eid,src] rows (512 B,
// warp-coalesced), accumulate in registers, fuse relu(h@W0 + sum) epilogue.
// d_out already holds h@W0 from the GEMM pass.
// ============================================================================
__global__ __launch_bounds__(256) void reduce_kernel(
    const float* __restrict__ norm, const int* __restrict__ src,
    const int* __restrict__ eid, float* __restrict__ out)
{
    const int w    = (blockIdx.x * blockDim.x + threadIdx.x) >> 5;
    const int lane = threadIdx.x & 31;
    if (w >= N_NODES) return;

    int i = g_start[w];
    const int end = g_start[w + 1];
    float4 acc = make_float4(0.f, 0.f, 0.f, 0.f);

    for (; i < end; i++) {
        const int   e  = g_edge_idx[i];
        const float nv = norm[e];
        const int   sn = src[e];
        const int   rr = eid[e];
        const float4 v = reinterpret_cast<const float4*>(
            g_all_h + ((size_t)rr * N_NODES + sn) * FEAT)[lane];
        acc.x = fmaf(v.x, nv, acc.x);
        acc.y = fmaf(v.y, nv, acc.y);
        acc.z = fmaf(v.z, nv, acc.z);
        acc.w = fmaf(v.w, nv, acc.w);
    }

    float4* op = reinterpret_cast<float4*>(out + (size_t)w * FEAT) + lane;
    float4 base = *op;   // h @ W0
    base.x = fmaxf(base.x + acc.x, 0.f);
    base.y = fmaxf(base.y + acc.y, 0.f);
    base.z = fmaxf(base.z + acc.z, 0.f);
    base.w = fmaxf(base.w + acc.w, 0.f);
    *op = base;
}

// ============================================================================
extern "C" void kernel_launch(void* const* d_in, const int* in_sizes, int n_in,
                              void* d_out, int out_size)
{
    const float* h      = (const float*)d_in[0];
    const float* weight = (const float*)d_in[1];
    const float* W0     = (const float*)d_in[2];
    const float* norm   = (const float*)d_in[3];
    const int*   src    = (const int*)d_in[4];
    const int*   dst    = (const int*)d_in[5];
    const int*   eid    = (const int*)d_in[6];
    float* out = (float*)d_out;
    (void)in_sizes; (void)n_in; (void)out_size;

    // Phase A: 6 GEMMs (r=0..4 -> all_h, r=5 -> h@W0 into d_out)
    dim3 gg((N_NODES + 127) / 128, NREL + 1);
    gemm_kernel<<<gg, 256>>>(h, weight, W0, out);

    // Phase B prep: CSR by dst
    zero_kernel<<<(N_NODES + 255) / 256, 256>>>();
    hist_kernel<<<(N_EDGES + 255) / 256, 256>>>(dst);
    scan_kernel<<<1, 1024>>>();
    scatter_kernel<<<(N_EDGES + 255) / 256, 256>>>(dst);

    // Phase B: gather-reduce + fused epilogue
    reduce_kernel<<<(N_NODES * 32 + 255) / 256, 256>>>(norm, src, eid, out);
}

// round 3
// speedup vs baseline: 2.1225x; 2.1225x over previous
#include <cuda_runtime.h>
#include <cuda_bf16.h>
#include <cstdint>
#include <cstddef>

#define N_NODES 100000
#define N_EDGES 600000
#define FEAT    128
#define NREL    5
#define NMAT    6          // 5 relations + W0

// ---------------- device-global scratch (allocation-free contract) ---------
__device__ float g_all_h[(size_t)NREL * N_NODES * FEAT];            // 256 MB
__device__ __nv_bfloat16 g_wbh[NMAT * FEAT * FEAT];                 // W^T hi, [r][n][k]
__device__ __nv_bfloat16 g_wbl[NMAT * FEAT * FEAT];                 // W^T lo
__device__ int   g_count[N_NODES];
__device__ int   g_cursor[N_NODES];
__device__ int   g_start[N_NODES + 1];
__device__ int   g_edge_idx[N_EDGES];
__device__ int   g_bsum[256];
__device__ int   g_boff[256];

// ---------------- helpers ----------------------------------------------------
static __device__ __forceinline__ uint32_t smem_u32(const void* p) {
    uint32_t a;
    asm("{ .reg .u64 t; cvta.to.shared.u64 t, %1; cvt.u32.u64 %0, t; }"
        : "=r"(a) : "l"(p));
    return a;
}

#define LDSM4(r0, r1, r2, r3, a)                                              \
    asm volatile("ldmatrix.sync.aligned.m8n8.x4.shared.b16 {%0,%1,%2,%3}, [%4];" \
                 : "=r"(r0), "=r"(r1), "=r"(r2), "=r"(r3) : "r"(a))

#define MMA_BF16(d, a, bb0, bb1)                                              \
    asm volatile("mma.sync.aligned.m16n8k16.row.col.f32.bf16.bf16.f32 "       \
                 "{%0,%1,%2,%3}, {%4,%5,%6,%7}, {%8,%9}, {%0,%1,%2,%3};"      \
                 : "+f"((d)[0]), "+f"((d)[1]), "+f"((d)[2]), "+f"((d)[3])     \
                 : "r"((a)[0]), "r"((a)[1]), "r"((a)[2]), "r"((a)[3]),        \
                   "r"(bb0), "r"(bb1))

#define CP_ASYNC16(dst, src)                                                  \
    asm volatile("cp.async.cg.shared.global [%0], [%1], 16;"                  \
                 :: "r"(dst), "l"(src) : "memory")
#define CP_COMMIT() asm volatile("cp.async.commit_group;" ::: "memory")

// ---------------- SMEM layout (bytes) ----------------------------------------
// padded row pitch: 136 bf16 = 272 B (bank-rotation 4 -> conflict-free ldmatrix)
#define APITCH   272u
#define A_HI_OFF 0u
#define A_LO_OFF 34816u          // 128*272
#define B_OFF    69632u          // 2 stages x (hi 34816 + lo 34816)
#define B_STAGE  69632u
#define B_KIND   34816u
#define SMEM_BYTES 208896u       // 69632 + 2*69632

// ============================================================================
// Weight pre-transpose + bf16 hi/lo split: g_wb*[r][n][k] = split(W_r[k][n])
// ============================================================================
__global__ void split_w_kernel(const float* __restrict__ weight,
                               const float* __restrict__ W0)
{
    const int r = blockIdx.x;
    const float* src = (r < NREL) ? (weight + (size_t)r * FEAT * FEAT) : W0;
    for (int i = threadIdx.x; i < FEAT * FEAT; i += blockDim.x) {
        const int k = i >> 7, n = i & 127;
        const float v = src[k * FEAT + n];
        const __nv_bfloat16 hi = __float2bfloat16(v);
        const __nv_bfloat16 lo = __float2bfloat16(v - __bfloat162float(hi));
        g_wbh[r * FEAT * FEAT + n * FEAT + k] = hi;
        g_wbl[r * FEAT * FEAT + n * FEAT + k] = lo;
    }
}

// ============================================================================
// mma.sync bf16 GEMM: one CTA = 128-row tile, loops over 6 relations.
// D = A_hi*B_hi + A_hi*B_lo + A_lo*B_hi  (3-term bf16 split, fp32 accum)
// ============================================================================
__global__ __launch_bounds__(256, 1)
void gemm_mma_kernel(const float* __restrict__ h, float* __restrict__ out)
{
    extern __shared__ __align__(1024) char smem[];
    const uint32_t sb  = smem_u32(smem);
    const int tid  = threadIdx.x;
    const int lane = tid & 31;
    const int warp = tid >> 5;
    const int wm   = warp & 1;          // m half (0/1)
    const int wn   = warp >> 1;         // n quarter (0..3)
    const int m0   = blockIdx.x * 128;
    const int m_warp = wm * 64;
    const int n_warp = wn * 32;

    // per-lane ldmatrix offsets
    const uint32_t a_off = (uint32_t)((((lane >> 3) & 1) * 8 + (lane & 7)) * APITCH
                                      + (lane >> 4) * 16);           // k_off*2
    const uint32_t b_off = (uint32_t)((((lane >> 4) * 8) + (lane & 7)) * APITCH
                                      + ((lane >> 3) & 1) * 16);

    // ---- issue cp.async for B(relation 0), stage 0 ----
    {
        #pragma unroll
        for (int i = 0; i < 16; i++) {
            const int q    = tid + i * 256;     // 4096 chunks of 16B
            const int kind = q >> 11;           // 0=hi, 1=lo
            const int rem  = q & 2047;
            const int n    = rem >> 4;
            const int ch   = rem & 15;
            const __nv_bfloat16* srcb = (kind == 0 ? g_wbh : g_wbl);
            const __nv_bfloat16* src  = srcb + 0 * FEAT * FEAT + n * FEAT + ch * 8;
            const uint32_t dst = sb + B_OFF + (uint32_t)kind * B_KIND
                               + (uint32_t)n * APITCH + (uint32_t)ch * 16u;
            CP_ASYNC16(dst, src);
        }
        CP_COMMIT();
    }

    // ---- load + split A tile (resident across all relations) ----
    #pragma unroll
    for (int i = 0; i < 16; i++) {
        const int q   = tid + i * 256;          // 4096 float4s
        const int row = q >> 5;
        const int f4  = q & 31;
        const int gm  = m0 + row;
        float4 v = make_float4(0.f, 0.f, 0.f, 0.f);
        if (gm < N_NODES)
            v = *reinterpret_cast<const float4*>(h + (size_t)gm * FEAT + f4 * 4);
        __nv_bfloat16 hx = __float2bfloat16(v.x);
        __nv_bfloat16 hy = __float2bfloat16(v.y);
        __nv_bfloat16 hz = __float2bfloat16(v.z);
        __nv_bfloat16 hw = __float2bfloat16(v.w);
        __nv_bfloat162 hi0 = __nv_bfloat162(hx, hy);
        __nv_bfloat162 hi1 = __nv_bfloat162(hz, hw);
        __nv_bfloat162 lo0 = __nv_bfloat162(
            __float2bfloat16(v.x - __bfloat162float(hx)),
            __float2bfloat16(v.y - __bfloat162float(hy)));
        __nv_bfloat162 lo1 = __nv_bfloat162(
            __float2bfloat16(v.z - __bfloat162float(hz)),
            __float2bfloat16(v.w - __bfloat162float(hw)));
        const uint32_t d = (uint32_t)(row * APITCH + f4 * 8);
        *reinterpret_cast<__nv_bfloat162*>(smem + A_HI_OFF + d)     = hi0;
        *reinterpret_cast<__nv_bfloat162*>(smem + A_HI_OFF + d + 4) = hi1;
        *reinterpret_cast<__nv_bfloat162*>(smem + A_LO_OFF + d)     = lo0;
        *reinterpret_cast<__nv_bfloat162*>(smem + A_LO_OFF + d + 4) = lo1;
    }

    // ---- relation loop ----
    #pragma unroll 1
    for (int r = 0; r < NMAT; r++) {
        const uint32_t stg = sb + B_OFF + (uint32_t)(r & 1) * B_STAGE;

        // prefetch B(r+1) into other stage
        if (r + 1 < NMAT) {
            const uint32_t nstg = sb + B_OFF + (uint32_t)((r + 1) & 1) * B_STAGE;
            #pragma unroll
            for (int i = 0; i < 16; i++) {
                const int q    = tid + i * 256;
                const int kind = q >> 11;
                const int rem  = q & 2047;
                const int n    = rem >> 4;
                const int ch   = rem & 15;
                const __nv_bfloat16* srcb = (kind == 0 ? g_wbh : g_wbl);
                const __nv_bfloat16* src  = srcb + (size_t)(r + 1) * FEAT * FEAT
                                          + n * FEAT + ch * 8;
                const uint32_t dst = nstg + (uint32_t)kind * B_KIND
                                   + (uint32_t)n * APITCH + (uint32_t)ch * 16u;
                CP_ASYNC16(dst, src);
            }
            CP_COMMIT();
            asm volatile("cp.async.wait_group 1;" ::: "memory");
        } else {
            asm volatile("cp.async.wait_group 0;" ::: "memory");
        }
        __syncthreads();   // B(r) visible to all; A visible on r==0

        float acc[4][4][4];
        #pragma unroll
        for (int i = 0; i < 4; i++)
            #pragma unroll
            for (int j = 0; j < 4; j++)
                #pragma unroll
                for (int q = 0; q < 4; q++) acc[i][j][q] = 0.f;

        const uint32_t aHi = sb + A_HI_OFF + (uint32_t)(m_warp * APITCH) + a_off;
        const uint32_t aLo = sb + A_LO_OFF + (uint32_t)(m_warp * APITCH) + a_off;
        const uint32_t bHi = stg + (uint32_t)(n_warp * APITCH) + b_off;
        const uint32_t bLo = bHi + B_KIND;

        #pragma unroll
        for (int ks = 0; ks < 8; ks++) {
            const uint32_t kb = (uint32_t)(ks * 32);   // k*2 bytes
            uint32_t ah[4][4], al[4][4], bh[2][4], bl[2][4];
            #pragma unroll
            for (int i = 0; i < 4; i++) {
                LDSM4(ah[i][0], ah[i][1], ah[i][2], ah[i][3],
                      aHi + (uint32_t)(i * 16 * APITCH) + kb);
                LDSM4(al[i][0], al[i][1], al[i][2], al[i][3],
                      aLo + (uint32_t)(i * 16 * APITCH) + kb);
            }
            #pragma unroll
            for (int j2 = 0; j2 < 2; j2++) {
                LDSM4(bh[j2][0], bh[j2][1], bh[j2][2], bh[j2][3],
                      bHi + (uint32_t)(j2 * 16 * APITCH) + kb);
                LDSM4(bl[j2][0], bl[j2][1], bl[j2][2], bl[j2][3],
                      bLo + (uint32_t)(j2 * 16 * APITCH) + kb);
            }
            #pragma unroll
            for (int i = 0; i < 4; i++) {
                #pragma unroll
                for (int j = 0; j < 4; j++) {
                    const int j2 = j >> 1, jj = (j & 1) * 2;
                    MMA_BF16(acc[i][j], ah[i], bh[j2][jj], bh[j2][jj + 1]);
                    MMA_BF16(acc[i][j], ah[i], bl[j2][jj], bl[j2][jj + 1]);
                    MMA_BF16(acc[i][j], al[i], bh[j2][jj], bh[j2][jj + 1]);
                }
            }
        }

        // ---- epilogue: direct STG.64 from accumulators ----
        float* __restrict__ C = (r == NREL) ? out
                              : (g_all_h + (size_t)r * N_NODES * FEAT);
        #pragma unroll
        for (int i = 0; i < 4; i++) {
            const int row0 = m0 + m_warp + i * 16 + (lane >> 2);
            #pragma unroll
            for (int j = 0; j < 4; j++) {
                const int c = n_warp + j * 8 + (lane & 3) * 2;
                if (row0 < N_NODES)
                    *reinterpret_cast<float2*>(C + (size_t)row0 * FEAT + c) =
                        make_float2(acc[i][j][0], acc[i][j][1]);
                if (row0 + 8 < N_NODES)
                    *reinterpret_cast<float2*>(C + (size_t)(row0 + 8) * FEAT + c) =
                        make_float2(acc[i][j][2], acc[i][j][3]);
            }
        }
        __syncthreads();   // protect B stage about to be overwritten next iter
    }
}

// ============================================================================
// CSR-by-dst build (parallel 3-phase scan)
// ============================================================================
__global__ void zero_kernel() {
    const int i = blockIdx.x * blockDim.x + threadIdx.x;
    if (i < N_NODES) { g_count[i] = 0; g_cursor[i] = 0; }
}

__global__ void hist_kernel(const int* __restrict__ dst) {
    const int e = blockIdx.x * blockDim.x + threadIdx.x;
    if (e < N_EDGES) atomicAdd(&g_count[dst[e]], 1);
}

#define SCAN_NB 196   // ceil(100000/512)

__global__ __launch_bounds__(512) void scan1_kernel() {
    __shared__ int sh[512];
    const int i = blockIdx.x * 512 + threadIdx.x;
    sh[threadIdx.x] = (i < N_NODES) ? g_count[i] : 0;
    __syncthreads();
    for (int off = 256; off > 0; off >>= 1) {
        if (threadIdx.x < off) sh[threadIdx.x] += sh[threadIdx.x + off];
        __syncthreads();
    }
    if (threadIdx.x == 0) g_bsum[blockIdx.x] = sh[0];
}

__global__ __launch_bounds__(256) void scan2_kernel() {
    __shared__ int sh[256];
    const int t = threadIdx.x;
    const int v = (t < SCAN_NB) ? g_bsum[t] : 0;
    sh[t] = v;
    __syncthreads();
    for (int off = 1; off < 256; off <<= 1) {
        int x = (t >= off) ? sh[t - off] : 0;
        __syncthreads();
        sh[t] += x;
        __syncthreads();
    }
    if (t < SCAN_NB) g_boff[t] = sh[t] - v;
    if (t == 255) g_start[N_NODES] = sh[255];
}

__global__ __launch_bounds__(512) void scan3_kernel() {
    __shared__ int sh[512];
    const int i = blockIdx.x * 512 + threadIdx.x;
    const int v = (i < N_NODES) ? g_count[i] : 0;
    sh[threadIdx.x] = v;
    __syncthreads();
    for (int off = 1; off < 512; off <<= 1) {
        int x = (threadIdx.x >= off) ? sh[threadIdx.x - off] : 0;
        __syncthreads();
        sh[threadIdx.x] += x;
        __syncthreads();
    }
    if (i < N_NODES) g_start[i] = g_boff[blockIdx.x] + sh[threadIdx.x] - v;
}

__global__ void scatter_kernel(const int* __restrict__ dst) {
    const int e = blockIdx.x * blockDim.x + threadIdx.x;
    if (e < N_EDGES) {
        const int d = dst[e];
        const int pos = g_start[d] + atomicAdd(&g_cursor[d], 1);
        g_edge_idx[pos] = e;
    }
}

// ============================================================================
// Gather-reduce + fused relu epilogue (one warp per dst node)
// ============================================================================
__global__ __launch_bounds__(256) void reduce_kernel(
    const float* __restrict__ norm, const int* __restrict__ src,
    const int* __restrict__ eid, float* __restrict__ out)
{
    const int w    = (blockIdx.x * blockDim.x + threadIdx.x) >> 5;
    const int lane = threadIdx.x & 31;
    if (w >= N_NODES) return;

    int i = g_start[w];
    const int end = g_start[w + 1];
    float4 acc = make_float4(0.f, 0.f, 0.f, 0.f);

    for (; i < end; i++) {
        const int   e  = g_edge_idx[i];
        const float nv = norm[e];
        const int   sn = src[e];
        const int   rr = eid[e];
        const float4 v = reinterpret_cast<const float4*>(
            g_all_h + ((size_t)rr * N_NODES + sn) * FEAT)[lane];
        acc.x = fmaf(v.x, nv, acc.x);
        acc.y = fmaf(v.y, nv, acc.y);
        acc.z = fmaf(v.z, nv, acc.z);
        acc.w = fmaf(v.w, nv, acc.w);
    }

    float4* op = reinterpret_cast<float4*>(out + (size_t)w * FEAT) + lane;
    float4 base = *op;   // h @ W0
    base.x = fmaxf(base.x + acc.x, 0.f);
    base.y = fmaxf(base.y + acc.y, 0.f);
    base.z = fmaxf(base.z + acc.z, 0.f);
    base.w = fmaxf(base.w + acc.w, 0.f);
    *op = base;
}

// ============================================================================
extern "C" void kernel_launch(void* const* d_in, const int* in_sizes, int n_in,
                              void* d_out, int out_size)
{
    const float* h      = (const float*)d_in[0];
    const float* weight = (const float*)d_in[1];
    const float* W0     = (const float*)d_in[2];
    const float* norm   = (const float*)d_in[3];
    const int*   src    = (const int*)d_in[4];
    const int*   dst    = (const int*)d_in[5];
    const int*   eid    = (const int*)d_in[6];
    float* out = (float*)d_out;
    (void)in_sizes; (void)n_in; (void)out_size;

    cudaFuncSetAttribute(gemm_mma_kernel,
                         cudaFuncAttributeMaxDynamicSharedMemorySize, SMEM_BYTES);

    // launch order: GEMM is launch index 5 so ncu (-s 5 -c 1) profiles it
    split_w_kernel<<<NMAT, 256>>>(weight, W0);                          // 0
    zero_kernel<<<(N_NODES + 255) / 256, 256>>>();                      // 1
    hist_kernel<<<(N_EDGES + 255) / 256, 256>>>(dst);                   // 2
    scan1_kernel<<<SCAN_NB, 512>>>();                                   // 3
    scan2_kernel<<<1, 256>>>();                                         // 4
    gemm_mma_kernel<<<(N_NODES + 127) / 128, 256, SMEM_BYTES>>>(h, out); // 5
    scan3_kernel<<<SCAN_NB, 512>>>();                                   // 6
    scatter_kernel<<<(N_EDGES + 255) / 256, 256>>>(dst);                // 7
    reduce_kernel<<<(N_NODES * 32 + 255) / 256, 256>>>(norm, src, eid, out); // 8
}

// round 4
// speedup vs baseline: 2.1355x; 1.0061x over previous
#include <cuda_runtime.h>
#include <cuda_bf16.h>
#include <cstdint>
#include <cstddef>

#define N_NODES 100000
#define N_EDGES 600000
#define FEAT    128
#define NREL    5
#define NMAT    6          // 5 relations + W0
#define NTILES  ((N_NODES + 127) / 128)   // 782
#define GEMM_GRID 148

// ---------------- device-global scratch (allocation-free contract) ---------
__device__ float g_all_h[(size_t)NREL * N_NODES * FEAT];            // 256 MB
__device__ __nv_bfloat16 g_wbh[NMAT * FEAT * FEAT];                 // W^T hi, [r][n][k]
__device__ __nv_bfloat16 g_wbl[NMAT * FEAT * FEAT];                 // W^T lo
__device__ int   g_count[N_NODES];
__device__ int   g_cursor[N_NODES];
__device__ int   g_start[N_NODES + 1];
__device__ int   g_row[N_EDGES];     // packed: eid*N_NODES + src, sorted by dst
__device__ float g_nrm[N_EDGES];     // norm, sorted by dst
__device__ int   g_bsum[256];
__device__ int   g_boff[256];

// ---------------- helpers ----------------------------------------------------
static __device__ __forceinline__ uint32_t smem_u32(const void* p) {
    uint32_t a;
    asm("{ .reg .u64 t; cvta.to.shared.u64 t, %1; cvt.u32.u64 %0, t; }"
        : "=r"(a) : "l"(p));
    return a;
}

#define LDSM4(r0, r1, r2, r3, a)                                              \
    asm volatile("ldmatrix.sync.aligned.m8n8.x4.shared.b16 {%0,%1,%2,%3}, [%4];" \
                 : "=r"(r0), "=r"(r1), "=r"(r2), "=r"(r3) : "r"(a))

#define MMA_BF16(d, a, bb0, bb1)                                              \
    asm volatile("mma.sync.aligned.m16n8k16.row.col.f32.bf16.bf16.f32 "       \
                 "{%0,%1,%2,%3}, {%4,%5,%6,%7}, {%8,%9}, {%0,%1,%2,%3};"      \
                 : "+f"((d)[0]), "+f"((d)[1]), "+f"((d)[2]), "+f"((d)[3])     \
                 : "r"((a)[0]), "r"((a)[1]), "r"((a)[2]), "r"((a)[3]),        \
                   "r"(bb0), "r"(bb1))

#define CP_ASYNC16(dst, src)                                                  \
    asm volatile("cp.async.cg.shared.global [%0], [%1], 16;"                  \
                 :: "r"(dst), "l"(src) : "memory")
#define CP_COMMIT() asm volatile("cp.async.commit_group;" ::: "memory")

// ---------------- SMEM layout (bytes) ----------------------------------------
// padded row pitch: 136 bf16 = 272 B (bank-rotation 4 -> conflict-free ldmatrix)
#define APITCH   272u
#define A_HI_OFF 0u
#define A_LO_OFF 34816u          // 128*272
#define B_OFF    69632u          // 2 stages x (hi 34816 + lo 34816)
#define B_STAGE  69632u
#define B_KIND   34816u
#define SMEM_BYTES 208896u       // 69632 + 2*69632

// ============================================================================
// Fused init: blocks 0..5 transpose+split weights; the rest zero counters.
// ============================================================================
#define ZERO_BLOCKS ((N_NODES + 255) / 256)
__global__ void init_kernel(const float* __restrict__ weight,
                            const float* __restrict__ W0)
{
    if (blockIdx.x < NMAT) {
        const int r = blockIdx.x;
        const float* src = (r < NREL) ? (weight + (size_t)r * FEAT * FEAT) : W0;
        for (int i = threadIdx.x; i < FEAT * FEAT; i += blockDim.x) {
            const int k = i >> 7, n = i & 127;
            const float v = src[k * FEAT + n];
            const __nv_bfloat16 hi = __float2bfloat16(v);
            const __nv_bfloat16 lo = __float2bfloat16(v - __bfloat162float(hi));
            g_wbh[r * FEAT * FEAT + n * FEAT + k] = hi;
            g_wbl[r * FEAT * FEAT + n * FEAT + k] = lo;
        }
    } else {
        const int i = (blockIdx.x - NMAT) * blockDim.x + threadIdx.x;
        if (i < N_NODES) { g_count[i] = 0; g_cursor[i] = 0; }
    }
}

// ============================================================================
// Persistent mma.sync bf16 GEMM: 148 CTAs loop over 782 tiles x 6 relations.
// D = A_hi*B_hi + A_hi*B_lo + A_lo*B_hi  (3-term bf16 split, fp32 accum)
// ============================================================================
__global__ __launch_bounds__(256, 1)
void gemm_mma_kernel(const float* __restrict__ h, float* __restrict__ out)
{
    extern __shared__ __align__(1024) char smem[];
    const uint32_t sb  = smem_u32(smem);
    const int tid  = threadIdx.x;
    const int lane = tid & 31;
    const int warp = tid >> 5;
    const int wm   = warp & 1;          // m half (0/1)
    const int wn   = warp >> 1;         // n quarter (0..3)
    const int m_warp = wm * 64;
    const int n_warp = wn * 32;

    // per-lane ldmatrix offsets
    const uint32_t a_off = (uint32_t)((((lane >> 3) & 1) * 8 + (lane & 7)) * APITCH
                                      + (lane >> 4) * 16);
    const uint32_t b_off = (uint32_t)((((lane >> 4) * 8) + (lane & 7)) * APITCH
                                      + ((lane >> 3) & 1) * 16);

    #pragma unroll 1
    for (int tile = blockIdx.x; tile < NTILES; tile += GEMM_GRID) {
        const int m0 = tile * 128;

        // ---- issue cp.async for B(relation 0), stage 0 (overlaps A load) ----
        #pragma unroll
        for (int i = 0; i < 16; i++) {
            const int q    = tid + i * 256;     // 4096 chunks of 16B
            const int kind = q >> 11;           // 0=hi, 1=lo
            const int rem  = q & 2047;
            const int n    = rem >> 4;
            const int ch   = rem & 15;
            const __nv_bfloat16* srcb = (kind == 0 ? g_wbh : g_wbl);
            const __nv_bfloat16* src  = srcb + n * FEAT + ch * 8;
            const uint32_t dst = sb + B_OFF + (uint32_t)kind * B_KIND
                               + (uint32_t)n * APITCH + (uint32_t)ch * 16u;
            CP_ASYNC16(dst, src);
        }
        CP_COMMIT();

        // ---- load + split A tile (resident across all relations) ----
        #pragma unroll
        for (int i = 0; i < 16; i++) {
            const int q   = tid + i * 256;          // 4096 float4s
            const int row = q >> 5;
            const int f4  = q & 31;
            const int gm  = m0 + row;
            float4 v = make_float4(0.f, 0.f, 0.f, 0.f);
            if (gm < N_NODES)
                v = *reinterpret_cast<const float4*>(h + (size_t)gm * FEAT + f4 * 4);
            __nv_bfloat16 hx = __float2bfloat16(v.x);
            __nv_bfloat16 hy = __float2bfloat16(v.y);
            __nv_bfloat16 hz = __float2bfloat16(v.z);
            __nv_bfloat16 hw = __float2bfloat16(v.w);
            __nv_bfloat162 hi0 = __nv_bfloat162(hx, hy);
            __nv_bfloat162 hi1 = __nv_bfloat162(hz, hw);
            __nv_bfloat162 lo0 = __nv_bfloat162(
                __float2bfloat16(v.x - __bfloat162float(hx)),
                __float2bfloat16(v.y - __bfloat162float(hy)));
            __nv_bfloat162 lo1 = __nv_bfloat162(
                __float2bfloat16(v.z - __bfloat162float(hz)),
                __float2bfloat16(v.w - __bfloat162float(hw)));
            const uint32_t d = (uint32_t)(row * APITCH + f4 * 8);
            *reinterpret_cast<__nv_bfloat162*>(smem + A_HI_OFF + d)     = hi0;
            *reinterpret_cast<__nv_bfloat162*>(smem + A_HI_OFF + d + 4) = hi1;
            *reinterpret_cast<__nv_bfloat162*>(smem + A_LO_OFF + d)     = lo0;
            *reinterpret_cast<__nv_bfloat162*>(smem + A_LO_OFF + d + 4) = lo1;
        }

        // ---- relation loop ----
        #pragma unroll 1
        for (int r = 0; r < NMAT; r++) {
            const uint32_t stg = sb + B_OFF + (uint32_t)(r & 1) * B_STAGE;

            // prefetch B(r+1) into other stage
            if (r + 1 < NMAT) {
                const uint32_t nstg = sb + B_OFF + (uint32_t)((r + 1) & 1) * B_STAGE;
                #pragma unroll
                for (int i = 0; i < 16; i++) {
                    const int q    = tid + i * 256;
                    const int kind = q >> 11;
                    const int rem  = q & 2047;
                    const int n    = rem >> 4;
                    const int ch   = rem & 15;
                    const __nv_bfloat16* srcb = (kind == 0 ? g_wbh : g_wbl);
                    const __nv_bfloat16* src  = srcb + (size_t)(r + 1) * FEAT * FEAT
                                              + n * FEAT + ch * 8;
                    const uint32_t dst = nstg + (uint32_t)kind * B_KIND
                                       + (uint32_t)n * APITCH + (uint32_t)ch * 16u;
                    CP_ASYNC16(dst, src);
                }
                CP_COMMIT();
                asm volatile("cp.async.wait_group 1;" ::: "memory");
            } else {
                asm volatile("cp.async.wait_group 0;" ::: "memory");
            }
            __syncthreads();   // B(r) + A visible to all

            float acc[4][4][4];
            #pragma unroll
            for (int i = 0; i < 4; i++)
                #pragma unroll
                for (int j = 0; j < 4; j++)
                    #pragma unroll
                    for (int q = 0; q < 4; q++) acc[i][j][q] = 0.f;

            const uint32_t aHi = sb + A_HI_OFF + (uint32_t)(m_warp * APITCH) + a_off;
            const uint32_t aLo = sb + A_LO_OFF + (uint32_t)(m_warp * APITCH) + a_off;
            const uint32_t bHi = stg + (uint32_t)(n_warp * APITCH) + b_off;
            const uint32_t bLo = bHi + B_KIND;

            #pragma unroll
            for (int ks = 0; ks < 8; ks++) {
                const uint32_t kb = (uint32_t)(ks * 32);
                uint32_t ah[4][4], al[4][4], bh[2][4], bl[2][4];
                #pragma unroll
                for (int i = 0; i < 4; i++) {
                    LDSM4(ah[i][0], ah[i][1], ah[i][2], ah[i][3],
                          aHi + (uint32_t)(i * 16 * APITCH) + kb);
                    LDSM4(al[i][0], al[i][1], al[i][2], al[i][3],
                          aLo + (uint32_t)(i * 16 * APITCH) + kb);
                }
                #pragma unroll
                for (int j2 = 0; j2 < 2; j2++) {
                    LDSM4(bh[j2][0], bh[j2][1], bh[j2][2], bh[j2][3],
                          bHi + (uint32_t)(j2 * 16 * APITCH) + kb);
                    LDSM4(bl[j2][0], bl[j2][1], bl[j2][2], bl[j2][3],
                          bLo + (uint32_t)(j2 * 16 * APITCH) + kb);
                }
                #pragma unroll
                for (int i = 0; i < 4; i++) {
                    #pragma unroll
                    for (int j = 0; j < 4; j++) {
                        const int j2 = j >> 1, jj = (j & 1) * 2;
                        MMA_BF16(acc[i][j], ah[i], bh[j2][jj], bh[j2][jj + 1]);
                        MMA_BF16(acc[i][j], ah[i], bl[j2][jj], bl[j2][jj + 1]);
                        MMA_BF16(acc[i][j], al[i], bh[j2][jj], bh[j2][jj + 1]);
                    }
                }
            }

            // ---- epilogue: direct STG.64 from accumulators ----
            float* __restrict__ C = (r == NREL) ? out
                                  : (g_all_h + (size_t)r * N_NODES * FEAT);
            #pragma unroll
            for (int i = 0; i < 4; i++) {
                const int row0 = m0 + m_warp + i * 16 + (lane >> 2);
                #pragma unroll
                for (int j = 0; j < 4; j++) {
                    const int c = n_warp + j * 8 + (lane & 3) * 2;
                    if (row0 < N_NODES)
                        *reinterpret_cast<float2*>(C + (size_t)row0 * FEAT + c) =
                            make_float2(acc[i][j][0], acc[i][j][1]);
                    if (row0 + 8 < N_NODES)
                        *reinterpret_cast<float2*>(C + (size_t)(row0 + 8) * FEAT + c) =
                            make_float2(acc[i][j][2], acc[i][j][3]);
                }
            }
            __syncthreads();   // protect B stage / A buffer about to be reused
        }
    }
}

// ============================================================================
// CSR-by-dst build (parallel 3-phase scan)
// ============================================================================
__global__ void hist_kernel(const int* __restrict__ dst) {
    const int e = blockIdx.x * blockDim.x + threadIdx.x;
    if (e < N_EDGES) atomicAdd(&g_count[dst[e]], 1);
}

#define SCAN_NB 196   // ceil(100000/512)

__global__ __launch_bounds__(512) void scan1_kernel() {
    __shared__ int sh[512];
    const int i = blockIdx.x * 512 + threadIdx.x;
    sh[threadIdx.x] = (i < N_NODES) ? g_count[i] : 0;
    __syncthreads();
    for (int off = 256; off > 0; off >>= 1) {
        if (threadIdx.x < off) sh[threadIdx.x] += sh[threadIdx.x + off];
        __syncthreads();
    }
    if (threadIdx.x == 0) g_bsum[blockIdx.x] = sh[0];
}

__global__ __launch_bounds__(256) void scan2_kernel() {
    __shared__ int sh[256];
    const int t = threadIdx.x;
    const int v = (t < SCAN_NB) ? g_bsum[t] : 0;
    sh[t] = v;
    __syncthreads();
    for (int off = 1; off < 256; off <<= 1) {
        int x = (t >= off) ? sh[t - off] : 0;
        __syncthreads();
        sh[t] += x;
        __syncthreads();
    }
    if (t < SCAN_NB) g_boff[t] = sh[t] - v;
    if (t == 255) g_start[N_NODES] = sh[255];
}

__global__ __launch_bounds__(512) void scan3_kernel() {
    __shared__ int sh[512];
    const int i = blockIdx.x * 512 + threadIdx.x;
    const int v = (i < N_NODES) ? g_count[i] : 0;
    sh[threadIdx.x] = v;
    __syncthreads();
    for (int off = 1; off < 512; off <<= 1) {
        int x = (threadIdx.x >= off) ? sh[threadIdx.x - off] : 0;
        __syncthreads();
        sh[threadIdx.x] += x;
        __syncthreads();
    }
    if (i < N_NODES) g_start[i] = g_boff[blockIdx.x] + sh[threadIdx.x] - v;
}

// scatter: write packed (row, norm) sorted by dst
__global__ void scatter_kernel(const int* __restrict__ dst,
                               const int* __restrict__ src,
                               const int* __restrict__ eid,
                               const float* __restrict__ norm) {
    const int e = blockIdx.x * blockDim.x + threadIdx.x;
    if (e < N_EDGES) {
        const int d = dst[e];
        const int pos = g_start[d] + atomicAdd(&g_cursor[d], 1);
        g_row[pos] = eid[e] * N_NODES + src[e];
        g_nrm[pos] = norm[e];
    }
}

// ============================================================================
// Gather-reduce + fused relu epilogue (one warp per dst node), 2-deep pipeline
// ============================================================================
__global__ __launch_bounds__(256) void reduce_kernel(float* __restrict__ out)
{
    const int w    = (blockIdx.x * blockDim.x + threadIdx.x) >> 5;
    const int lane = threadIdx.x & 31;
    if (w >= N_NODES) return;

    int i = g_start[w];
    const int end = g_start[w + 1];
    float4 acc = make_float4(0.f, 0.f, 0.f, 0.f);

    if (i < end) {
        int   r0 = g_row[i];
        float n0 = g_nrm[i];
        #pragma unroll 2
        for (; i + 1 < end; i++) {
            const int   r1 = g_row[i + 1];
            const float n1 = g_nrm[i + 1];
            const float4 v = reinterpret_cast<const float4*>(
                g_all_h + (size_t)r0 * FEAT)[lane];
            acc.x = fmaf(v.x, n0, acc.x);
            acc.y = fmaf(v.y, n0, acc.y);
            acc.z = fmaf(v.z, n0, acc.z);
            acc.w = fmaf(v.w, n0, acc.w);
            r0 = r1; n0 = n1;
        }
        const float4 v = reinterpret_cast<const float4*>(
            g_all_h + (size_t)r0 * FEAT)[lane];
        acc.x = fmaf(v.x, n0, acc.x);
        acc.y = fmaf(v.y, n0, acc.y);
        acc.z = fmaf(v.z, n0, acc.z);
        acc.w = fmaf(v.w, n0, acc.w);
    }

    float4* op = reinterpret_cast<float4*>(out + (size_t)w * FEAT) + lane;
    float4 base = *op;   // h @ W0
    base.x = fmaxf(base.x + acc.x, 0.f);
    base.y = fmaxf(base.y + acc.y, 0.f);
    base.z = fmaxf(base.z + acc.z, 0.f);
    base.w = fmaxf(base.w + acc.w, 0.f);
    *op = base;
}

// ============================================================================
extern "C" void kernel_launch(void* const* d_in, const int* in_sizes, int n_in,
                              void* d_out, int out_size)
{
    const float* h      = (const float*)d_in[0];
    const float* weight = (const float*)d_in[1];
    const float* W0     = (const float*)d_in[2];
    const float* norm   = (const float*)d_in[3];
    const int*   src    = (const int*)d_in[4];
    const int*   dst    = (const int*)d_in[5];
    const int*   eid    = (const int*)d_in[6];
    float* out = (float*)d_out;
    (void)in_sizes; (void)n_in; (void)out_size;

    cudaFuncSetAttribute(gemm_mma_kernel,
                         cudaFuncAttributeMaxDynamicSharedMemorySize, SMEM_BYTES);

    init_kernel<<<NMAT + ZERO_BLOCKS, 256>>>(weight, W0);               // 0
    hist_kernel<<<(N_EDGES + 255) / 256, 256>>>(dst);                   // 1
    scan1_kernel<<<SCAN_NB, 512>>>();                                   // 2
    scan2_kernel<<<1, 256>>>();                                         // 3
    scan3_kernel<<<SCAN_NB, 512>>>();                                   // 4
    gemm_mma_kernel<<<GEMM_GRID, 256, SMEM_BYTES>>>(h, out);            // 5
    scatter_kernel<<<(N_EDGES + 255) / 256, 256>>>(dst, src, eid, norm);// 6
    reduce_kernel<<<(N_NODES * 32 + 255) / 256, 256>>>(out);            // 7
}

// round 5
// speedup vs baseline: 2.2328x; 1.0456x over previous
#include <cuda_runtime.h>
#include <cuda_bf16.h>
#include <cstdint>
#include <cstddef>

#define N_NODES 100000
#define N_EDGES 600000
#define FEAT    128
#define NREL    5
#define NMAT    6          // 5 relations + W0
#define NTILES  ((N_NODES + 127) / 128)   // 782
#define GEMM_GRID 148

// ---------------- device-global scratch (allocation-free contract) ---------
__device__ float g_all_h[(size_t)NREL * N_NODES * FEAT];            // 256 MB
__device__ __nv_bfloat16 g_wbh[NMAT * FEAT * FEAT];                 // W^T hi, [r][n][k]
__device__ __nv_bfloat16 g_wbl[NMAT * FEAT * FEAT];                 // W^T lo
__device__ int   g_count[N_NODES];
__device__ int   g_cursor[N_NODES];
__device__ int   g_start[N_NODES + 1];
__device__ int   g_row[N_EDGES];     // packed: eid*N_NODES + src, sorted by dst
__device__ float g_nrm[N_EDGES];     // norm, sorted by dst
__device__ int   g_bsum[256];
__device__ int   g_boff[256];

// ---------------- helpers ----------------------------------------------------
static __device__ __forceinline__ uint32_t smem_u32(const void* p) {
    uint32_t a;
    asm("{ .reg .u64 t; cvta.to.shared.u64 t, %1; cvt.u32.u64 %0, t; }"
        : "=r"(a) : "l"(p));
    return a;
}

#define LDSM4(r0, r1, r2, r3, a)                                              \
    asm volatile("ldmatrix.sync.aligned.m8n8.x4.shared.b16 {%0,%1,%2,%3}, [%4];" \
                 : "=r"(r0), "=r"(r1), "=r"(r2), "=r"(r3) : "r"(a))

#define MMA_BF16(d, a, bb0, bb1)                                              \
    asm volatile("mma.sync.aligned.m16n8k16.row.col.f32.bf16.bf16.f32 "       \
                 "{%0,%1,%2,%3}, {%4,%5,%6,%7}, {%8,%9}, {%0,%1,%2,%3};"      \
                 : "+f"((d)[0]), "+f"((d)[1]), "+f"((d)[2]), "+f"((d)[3])     \
                 : "r"((a)[0]), "r"((a)[1]), "r"((a)[2]), "r"((a)[3]),        \
                   "r"(bb0), "r"(bb1))

#define CP_ASYNC16(dst, src)                                                  \
    asm volatile("cp.async.cg.shared.global [%0], [%1], 16;"                  \
                 :: "r"(dst), "l"(src) : "memory")
#define CP_COMMIT() asm volatile("cp.async.commit_group;" ::: "memory")

// ---------------- SMEM layout (bytes) ----------------------------------------
#define APITCH   272u
#define A_HI_OFF 0u
#define A_LO_OFF 34816u          // 128*272
#define B_OFF    69632u          // 2 stages x (hi 34816 + lo 34816)
#define B_STAGE  69632u
#define B_KIND   34816u
#define SMEM_BYTES 208896u

// ============================================================================
// Fused init: blocks 0..5 transpose+split weights; the rest zero counters.
// ============================================================================
#define ZERO_BLOCKS ((N_NODES + 255) / 256)
__global__ void init_kernel(const float* __restrict__ weight,
                            const float* __restrict__ W0)
{
    if (blockIdx.x < NMAT) {
        const int r = blockIdx.x;
        const float* src = (r < NREL) ? (weight + (size_t)r * FEAT * FEAT) : W0;
        for (int i = threadIdx.x; i < FEAT * FEAT; i += blockDim.x) {
            const int k = i >> 7, n = i & 127;
            const float v = src[k * FEAT + n];
            const __nv_bfloat16 hi = __float2bfloat16(v);
            const __nv_bfloat16 lo = __float2bfloat16(v - __bfloat162float(hi));
            g_wbh[r * FEAT * FEAT + n * FEAT + k] = hi;
            g_wbl[r * FEAT * FEAT + n * FEAT + k] = lo;
        }
    } else {
        const int i = (blockIdx.x - NMAT) * blockDim.x + threadIdx.x;
        if (i < N_NODES) { g_count[i] = 0; g_cursor[i] = 0; }
    }
}

// ============================================================================
// Persistent mma.sync bf16 GEMM: 148 CTAs loop over 782 tiles x 6 relations.
// D = A_hi*B_hi + A_hi*B_lo + A_lo*B_hi  (3-term bf16 split, fp32 accum)
// ============================================================================
__global__ __launch_bounds__(256, 1)
void gemm_mma_kernel(const float* __restrict__ h, float* __restrict__ out)
{
    extern __shared__ __align__(1024) char smem[];
    const uint32_t sb  = smem_u32(smem);
    const int tid  = threadIdx.x;
    const int lane = tid & 31;
    const int warp = tid >> 5;
    const int wm   = warp & 1;
    const int wn   = warp >> 1;
    const int m_warp = wm * 64;
    const int n_warp = wn * 32;

    const uint32_t a_off = (uint32_t)((((lane >> 3) & 1) * 8 + (lane & 7)) * APITCH
                                      + (lane >> 4) * 16);
    const uint32_t b_off = (uint32_t)((((lane >> 4) * 8) + (lane & 7)) * APITCH
                                      + ((lane >> 3) & 1) * 16);

    #pragma unroll 1
    for (int tile = blockIdx.x; tile < NTILES; tile += GEMM_GRID) {
        const int m0 = tile * 128;

        // ---- issue cp.async for B(relation 0), stage 0 (overlaps A load) ----
        #pragma unroll
        for (int i = 0; i < 16; i++) {
            const int q    = tid + i * 256;
            const int kind = q >> 11;
            const int rem  = q & 2047;
            const int n    = rem >> 4;
            const int ch   = rem & 15;
            const __nv_bfloat16* srcb = (kind == 0 ? g_wbh : g_wbl);
            const __nv_bfloat16* src  = srcb + n * FEAT + ch * 8;
            const uint32_t dst = sb + B_OFF + (uint32_t)kind * B_KIND
                               + (uint32_t)n * APITCH + (uint32_t)ch * 16u;
            CP_ASYNC16(dst, src);
        }
        CP_COMMIT();

        // ---- load + split A tile (resident across all relations) ----
        #pragma unroll
        for (int i = 0; i < 16; i++) {
            const int q   = tid + i * 256;
            const int row = q >> 5;
            const int f4  = q & 31;
            const int gm  = m0 + row;
            float4 v = make_float4(0.f, 0.f, 0.f, 0.f);
            if (gm < N_NODES)
                v = *reinterpret_cast<const float4*>(h + (size_t)gm * FEAT + f4 * 4);
            __nv_bfloat16 hx = __float2bfloat16(v.x);
            __nv_bfloat16 hy = __float2bfloat16(v.y);
            __nv_bfloat16 hz = __float2bfloat16(v.z);
            __nv_bfloat16 hw = __float2bfloat16(v.w);
            __nv_bfloat162 hi0 = __nv_bfloat162(hx, hy);
            __nv_bfloat162 hi1 = __nv_bfloat162(hz, hw);
            __nv_bfloat162 lo0 = __nv_bfloat162(
                __float2bfloat16(v.x - __bfloat162float(hx)),
                __float2bfloat16(v.y - __bfloat162float(hy)));
            __nv_bfloat162 lo1 = __nv_bfloat162(
                __float2bfloat16(v.z - __bfloat162float(hz)),
                __float2bfloat16(v.w - __bfloat162float(hw)));
            const uint32_t d = (uint32_t)(row * APITCH + f4 * 8);
            *reinterpret_cast<__nv_bfloat162*>(smem + A_HI_OFF + d)     = hi0;
            *reinterpret_cast<__nv_bfloat162*>(smem + A_HI_OFF + d + 4) = hi1;
            *reinterpret_cast<__nv_bfloat162*>(smem + A_LO_OFF + d)     = lo0;
            *reinterpret_cast<__nv_bfloat162*>(smem + A_LO_OFF + d + 4) = lo1;
        }

        // ---- relation loop ----
        #pragma unroll 1
        for (int r = 0; r < NMAT; r++) {
            const uint32_t stg = sb + B_OFF + (uint32_t)(r & 1) * B_STAGE;

            if (r + 1 < NMAT) {
                const uint32_t nstg = sb + B_OFF + (uint32_t)((r + 1) & 1) * B_STAGE;
                #pragma unroll
                for (int i = 0; i < 16; i++) {
                    const int q    = tid + i * 256;
                    const int kind = q >> 11;
                    const int rem  = q & 2047;
                    const int n    = rem >> 4;
                    const int ch   = rem & 15;
                    const __nv_bfloat16* srcb = (kind == 0 ? g_wbh : g_wbl);
                    const __nv_bfloat16* src  = srcb + (size_t)(r + 1) * FEAT * FEAT
                                              + n * FEAT + ch * 8;
                    const uint32_t dst = nstg + (uint32_t)kind * B_KIND
                                       + (uint32_t)n * APITCH + (uint32_t)ch * 16u;
                    CP_ASYNC16(dst, src);
                }
                CP_COMMIT();
                asm volatile("cp.async.wait_group 1;" ::: "memory");
            } else {
                asm volatile("cp.async.wait_group 0;" ::: "memory");
            }
            __syncthreads();

            float acc[4][4][4];
            #pragma unroll
            for (int i = 0; i < 4; i++)
                #pragma unroll
                for (int j = 0; j < 4; j++)
                    #pragma unroll
                    for (int q = 0; q < 4; q++) acc[i][j][q] = 0.f;

            const uint32_t aHi = sb + A_HI_OFF + (uint32_t)(m_warp * APITCH) + a_off;
            const uint32_t aLo = sb + A_LO_OFF + (uint32_t)(m_warp * APITCH) + a_off;
            const uint32_t bHi = stg + (uint32_t)(n_warp * APITCH) + b_off;
            const uint32_t bLo = bHi + B_KIND;

            #pragma unroll
            for (int ks = 0; ks < 8; ks++) {
                const uint32_t kb = (uint32_t)(ks * 32);
                uint32_t ah[4][4], al[4][4], bh[2][4], bl[2][4];
                #pragma unroll
                for (int i = 0; i < 4; i++) {
                    LDSM4(ah[i][0], ah[i][1], ah[i][2], ah[i][3],
                          aHi + (uint32_t)(i * 16 * APITCH) + kb);
                    LDSM4(al[i][0], al[i][1], al[i][2], al[i][3],
                          aLo + (uint32_t)(i * 16 * APITCH) + kb);
                }
                #pragma unroll
                for (int j2 = 0; j2 < 2; j2++) {
                    LDSM4(bh[j2][0], bh[j2][1], bh[j2][2], bh[j2][3],
                          bHi + (uint32_t)(j2 * 16 * APITCH) + kb);
                    LDSM4(bl[j2][0], bl[j2][1], bl[j2][2], bl[j2][3],
                          bLo + (uint32_t)(j2 * 16 * APITCH) + kb);
                }
                #pragma unroll
                for (int i = 0; i < 4; i++) {
                    #pragma unroll
                    for (int j = 0; j < 4; j++) {
                        const int j2 = j >> 1, jj = (j & 1) * 2;
                        MMA_BF16(acc[i][j], ah[i], bh[j2][jj], bh[j2][jj + 1]);
                        MMA_BF16(acc[i][j], ah[i], bl[j2][jj], bl[j2][jj + 1]);
                        MMA_BF16(acc[i][j], al[i], bh[j2][jj], bh[j2][jj + 1]);
                    }
                }
            }

            float* __restrict__ C = (r == NREL) ? out
                                  : (g_all_h + (size_t)r * N_NODES * FEAT);
            #pragma unroll
            for (int i = 0; i < 4; i++) {
                const int row0 = m0 + m_warp + i * 16 + (lane >> 2);
                #pragma unroll
                for (int j = 0; j < 4; j++) {
                    const int c = n_warp + j * 8 + (lane & 3) * 2;
                    if (row0 < N_NODES)
                        *reinterpret_cast<float2*>(C + (size_t)row0 * FEAT + c) =
                            make_float2(acc[i][j][0], acc[i][j][1]);
                    if (row0 + 8 < N_NODES)
                        *reinterpret_cast<float2*>(C + (size_t)(row0 + 8) * FEAT + c) =
                            make_float2(acc[i][j][2], acc[i][j][3]);
                }
            }
            __syncthreads();
        }
    }
}

// ============================================================================
// CSR-by-dst build (parallel 3-phase scan)
// ============================================================================
__global__ void hist_kernel(const int* __restrict__ dst) {
    const int e = blockIdx.x * blockDim.x + threadIdx.x;
    if (e < N_EDGES) atomicAdd(&g_count[dst[e]], 1);
}

#define SCAN_NB 196   // ceil(100000/512)

__global__ __launch_bounds__(512) void scan1_kernel() {
    __shared__ int sh[512];
    const int i = blockIdx.x * 512 + threadIdx.x;
    sh[threadIdx.x] = (i < N_NODES) ? g_count[i] : 0;
    __syncthreads();
    for (int off = 256; off > 0; off >>= 1) {
        if (threadIdx.x < off) sh[threadIdx.x] += sh[threadIdx.x + off];
        __syncthreads();
    }
    if (threadIdx.x == 0) g_bsum[blockIdx.x] = sh[0];
}

__global__ __launch_bounds__(256) void scan2_kernel() {
    __shared__ int sh[256];
    const int t = threadIdx.x;
    const int v = (t < SCAN_NB) ? g_bsum[t] : 0;
    sh[t] = v;
    __syncthreads();
    for (int off = 1; off < 256; off <<= 1) {
        int x = (t >= off) ? sh[t - off] : 0;
        __syncthreads();
        sh[t] += x;
        __syncthreads();
    }
    if (t < SCAN_NB) g_boff[t] = sh[t] - v;
    if (t == 255) g_start[N_NODES] = sh[255];
}

__global__ __launch_bounds__(512) void scan3_kernel() {
    __shared__ int sh[512];
    const int i = blockIdx.x * 512 + threadIdx.x;
    const int v = (i < N_NODES) ? g_count[i] : 0;
    sh[threadIdx.x] = v;
    __syncthreads();
    for (int off = 1; off < 512; off <<= 1) {
        int x = (threadIdx.x >= off) ? sh[threadIdx.x - off] : 0;
        __syncthreads();
        sh[threadIdx.x] += x;
        __syncthreads();
    }
    if (i < N_NODES) g_start[i] = g_boff[blockIdx.x] + sh[threadIdx.x] - v;
}

__global__ void scatter_kernel(const int* __restrict__ dst,
                               const int* __restrict__ src,
                               const int* __restrict__ eid,
                               const float* __restrict__ norm) {
    const int e = blockIdx.x * blockDim.x + threadIdx.x;
    if (e < N_EDGES) {
        const int d = dst[e];
        const int pos = g_start[d] + atomicAdd(&g_cursor[d], 1);
        g_row[pos] = eid[e] * N_NODES + src[e];
        g_nrm[pos] = norm[e];
    }
}

// ============================================================================
// Gather-reduce + fused relu epilogue (one warp per dst node), 2-deep pipeline
// ============================================================================
__global__ __launch_bounds__(256) void reduce_kernel(float* __restrict__ out)
{
    const int w    = (blockIdx.x * blockDim.x + threadIdx.x) >> 5;
    const int lane = threadIdx.x & 31;
    if (w >= N_NODES) return;

    int i = g_start[w];
    const int end = g_start[w + 1];
    float4 acc = make_float4(0.f, 0.f, 0.f, 0.f);

    if (i < end) {
        int   r0 = g_row[i];
        float n0 = g_nrm[i];
        #pragma unroll 2
        for (; i + 1 < end; i++) {
            const int   r1 = g_row[i + 1];
            const float n1 = g_nrm[i + 1];
            const float4 v = reinterpret_cast<const float4*>(
                g_all_h + (size_t)r0 * FEAT)[lane];
            acc.x = fmaf(v.x, n0, acc.x);
            acc.y = fmaf(v.y, n0, acc.y);
            acc.z = fmaf(v.z, n0, acc.z);
            acc.w = fmaf(v.w, n0, acc.w);
            r0 = r1; n0 = n1;
        }
        const float4 v = reinterpret_cast<const float4*>(
            g_all_h + (size_t)r0 * FEAT)[lane];
        acc.x = fmaf(v.x, n0, acc.x);
        acc.y = fmaf(v.y, n0, acc.y);
        acc.z = fmaf(v.z, n0, acc.z);
        acc.w = fmaf(v.w, n0, acc.w);
    }

    float4* op = reinterpret_cast<float4*>(out + (size_t)w * FEAT) + lane;
    float4 base = *op;   // h @ W0
    base.x = fmaxf(base.x + acc.x, 0.f);
    base.y = fmaxf(base.y + acc.y, 0.f);
    base.z = fmaxf(base.z + acc.z, 0.f);
    base.w = fmaxf(base.w + acc.w, 0.f);
    *op = base;
}

// ============================================================================
extern "C" void kernel_launch(void* const* d_in, const int* in_sizes, int n_in,
                              void* d_out, int out_size)
{
    const float* h      = (const float*)d_in[0];
    const float* weight = (const float*)d_in[1];
    const float* W0     = (const float*)d_in[2];
    const float* norm   = (const float*)d_in[3];
    const int*   src    = (const int*)d_in[4];
    const int*   dst    = (const int*)d_in[5];
    const int*   eid    = (const int*)d_in[6];
    float* out = (float*)d_out;
    (void)in_sizes; (void)n_in; (void)out_size;

    cudaFuncSetAttribute(gemm_mma_kernel,
                         cudaFuncAttributeMaxDynamicSharedMemorySize, SMEM_BYTES);

    // Side stream + events, created once on the (uncaptured) correctness call,
    // reused during graph capture. Fork lets the CSR-prep chain run
    // concurrently with the GEMM; join before reduce.
    static cudaStream_t s2 = nullptr;
    static cudaEvent_t  evFork = nullptr, evJoin = nullptr;
    if (s2 == nullptr) {
        if (cudaStreamCreateWithFlags(&s2, cudaStreamNonBlocking) != cudaSuccess)
            s2 = nullptr;
        if (s2) {
            cudaEventCreateWithFlags(&evFork, cudaEventDisableTiming);
            cudaEventCreateWithFlags(&evJoin, cudaEventDisableTiming);
        }
    }

    init_kernel<<<NMAT + ZERO_BLOCKS, 256>>>(weight, W0);

    if (s2) {
        cudaEventRecord(evFork, 0);
        cudaStreamWaitEvent(s2, evFork, 0);

        // main stream: the big GEMM
        gemm_mma_kernel<<<GEMM_GRID, 256, SMEM_BYTES>>>(h, out);

        // side stream: CSR prep chain (disjoint buffers from the GEMM)
        hist_kernel<<<(N_EDGES + 255) / 256, 256, 0, s2>>>(dst);
        scan1_kernel<<<SCAN_NB, 512, 0, s2>>>();
        scan2_kernel<<<1, 256, 0, s2>>>();
        scan3_kernel<<<SCAN_NB, 512, 0, s2>>>();
        scatter_kernel<<<(N_EDGES + 255) / 256, 256, 0, s2>>>(dst, src, eid, norm);

        cudaEventRecord(evJoin, s2);
        cudaStreamWaitEvent(0, evJoin, 0);
    } else {
        // fallback: sequential
        hist_kernel<<<(N_EDGES + 255) / 256, 256>>>(dst);
        scan1_kernel<<<SCAN_NB, 512>>>();
        scan2_kernel<<<1, 256>>>();
        scan3_kernel<<<SCAN_NB, 512>>>();
        gemm_mma_kernel<<<GEMM_GRID, 256, SMEM_BYTES>>>(h, out);
        scatter_kernel<<<(N_EDGES + 255) / 256, 256>>>(dst, src, eid, norm);
    }

    reduce_kernel<<<(N_NODES * 32 + 255) / 256, 256>>>(out);
}

// round 6
// speedup vs baseline: 3.1723x; 1.4208x over previous
#include <cuda_runtime.h>
#include <cuda_fp16.h>
#include <cstdint>
#include <cstddef>

#define N_NODES 100000
#define N_EDGES 600000
#define FEAT    128
#define NREL    5
#define NMAT    6          // 5 relations + W0
#define NTILES  ((N_NODES + 127) / 128)   // 782
#define GEMM_GRID 148

// ---------------- device-global scratch (allocation-free contract) ---------
__device__ __half g_all_h[(size_t)NREL * N_NODES * FEAT];           // 128 MB, fp16
__device__ __half g_wfh[NMAT * FEAT * FEAT];                        // W^T fp16, [r][n][k]
__device__ int   g_count[N_NODES];
__device__ int   g_cursor[N_NODES];
__device__ int   g_start[N_NODES + 1];
__device__ int   g_row[N_EDGES];     // packed: eid*N_NODES + src, sorted by dst
__device__ float g_nrm[N_EDGES];     // norm, sorted by dst
__device__ int   g_bsum[256];
__device__ int   g_boff[256];

// ---------------- helpers ----------------------------------------------------
static __device__ __forceinline__ uint32_t smem_u32(const void* p) {
    uint32_t a;
    asm("{ .reg .u64 t; cvta.to.shared.u64 t, %1; cvt.u32.u64 %0, t; }"
        : "=r"(a) : "l"(p));
    return a;
}

#define LDSM4(r0, r1, r2, r3, a)                                              \
    asm volatile("ldmatrix.sync.aligned.m8n8.x4.shared.b16 {%0,%1,%2,%3}, [%4];" \
                 : "=r"(r0), "=r"(r1), "=r"(r2), "=r"(r3) : "r"(a))

#define MMA_F16(d, a, bb0, bb1)                                               \
    asm volatile("mma.sync.aligned.m16n8k16.row.col.f32.f16.f16.f32 "         \
                 "{%0,%1,%2,%3}, {%4,%5,%6,%7}, {%8,%9}, {%0,%1,%2,%3};"      \
                 : "+f"((d)[0]), "+f"((d)[1]), "+f"((d)[2]), "+f"((d)[3])     \
                 : "r"((a)[0]), "r"((a)[1]), "r"((a)[2]), "r"((a)[3]),        \
                   "r"(bb0), "r"(bb1))

#define CP_ASYNC16(dst, src)                                                  \
    asm volatile("cp.async.cg.shared.global [%0], [%1], 16;"                  \
                 :: "r"(dst), "l"(src) : "memory")
#define CP_COMMIT() asm volatile("cp.async.commit_group;" ::: "memory")

// ---------------- SMEM layout (bytes) ----------------------------------------
// padded row pitch: 136 fp16 = 272 B (bank-rotation 4 -> conflict-free ldmatrix)
#define APITCH   272u
#define A_HI_OFF 0u
#define A_LO_OFF 34816u          // 128*272
#define B_OFF    69632u          // 2 stages x 34816 (B hi only)
#define B_STAGE  34816u
#define SMEM_BYTES 139264u       // 69632 + 2*34816

// ============================================================================
// Fused init: blocks 0..5 transpose weights to fp16; the rest zero counters.
// ============================================================================
#define ZERO_BLOCKS ((N_NODES + 255) / 256)
__global__ void init_kernel(const float* __restrict__ weight,
                            const float* __restrict__ W0)
{
    if (blockIdx.x < NMAT) {
        const int r = blockIdx.x;
        const float* src = (r < NREL) ? (weight + (size_t)r * FEAT * FEAT) : W0;
        for (int i = threadIdx.x; i < FEAT * FEAT; i += blockDim.x) {
            const int k = i >> 7, n = i & 127;
            g_wfh[r * FEAT * FEAT + n * FEAT + k] = __float2half_rn(src[k * FEAT + n]);
        }
    } else {
        const int i = (blockIdx.x - NMAT) * blockDim.x + threadIdx.x;
        if (i < N_NODES) { g_count[i] = 0; g_cursor[i] = 0; }
    }
}

// ============================================================================
// Persistent mma.sync fp16 GEMM: 148 CTAs loop over 782 tiles x 6 relations.
// D = (A_hi + A_lo) * B_hi   (fp16 2-term split of A, B single fp16, fp32 acc)
// r<5 -> g_all_h (fp16), r==5 -> out (fp32, h@W0)
// ============================================================================
__global__ __launch_bounds__(256, 1)
void gemm_mma_kernel(const float* __restrict__ h, float* __restrict__ out)
{
    extern __shared__ __align__(1024) char smem[];
    const uint32_t sb  = smem_u32(smem);
    const int tid  = threadIdx.x;
    const int lane = tid & 31;
    const int warp = tid >> 5;
    const int wm   = warp & 1;          // m half (0/1)
    const int wn   = warp >> 1;         // n quarter (0..3)
    const int m_warp = wm * 64;
    const int n_warp = wn * 32;

    const uint32_t a_off = (uint32_t)((((lane >> 3) & 1) * 8 + (lane & 7)) * APITCH
                                      + (lane >> 4) * 16);
    const uint32_t b_off = (uint32_t)((((lane >> 4) * 8) + (lane & 7)) * APITCH
                                      + ((lane >> 3) & 1) * 16);

    #pragma unroll 1
    for (int tile = blockIdx.x; tile < NTILES; tile += GEMM_GRID) {
        const int m0 = tile * 128;

        // ---- cp.async B(relation 0) into stage 0 (overlaps A load) ----
        #pragma unroll
        for (int i = 0; i < 8; i++) {
            const int q  = tid + i * 256;       // 2048 chunks of 16B
            const int n  = q >> 4;
            const int ch = q & 15;
            const __half* src = g_wfh + n * FEAT + ch * 8;
            const uint32_t dst = sb + B_OFF + (uint32_t)n * APITCH + (uint32_t)ch * 16u;
            CP_ASYNC16(dst, src);
        }
        CP_COMMIT();

        // ---- load + split A tile into fp16 hi/lo (resident across relations) ----
        #pragma unroll
        for (int i = 0; i < 16; i++) {
            const int q   = tid + i * 256;      // 4096 float4s
            const int row = q >> 5;
            const int f4  = q & 31;
            const int gm  = m0 + row;
            float4 v = make_float4(0.f, 0.f, 0.f, 0.f);
            if (gm < N_NODES)
                v = *reinterpret_cast<const float4*>(h + (size_t)gm * FEAT + f4 * 4);
            const __half hx = __float2half_rn(v.x);
            const __half hy = __float2half_rn(v.y);
            const __half hz = __float2half_rn(v.z);
            const __half hw = __float2half_rn(v.w);
            const __half2 hi0 = __halves2half2(hx, hy);
            const __half2 hi1 = __halves2half2(hz, hw);
            const __half2 lo0 = __halves2half2(
                __float2half_rn(v.x - __half2float(hx)),
                __float2half_rn(v.y - __half2float(hy)));
            const __half2 lo1 = __halves2half2(
                __float2half_rn(v.z - __half2float(hz)),
                __float2half_rn(v.w - __half2float(hw)));
            const uint32_t d = (uint32_t)(row * APITCH + f4 * 8);
            *reinterpret_cast<__half2*>(smem + A_HI_OFF + d)     = hi0;
            *reinterpret_cast<__half2*>(smem + A_HI_OFF + d + 4) = hi1;
            *reinterpret_cast<__half2*>(smem + A_LO_OFF + d)     = lo0;
            *reinterpret_cast<__half2*>(smem + A_LO_OFF + d + 4) = lo1;
        }

        // ---- relation loop ----
        #pragma unroll 1
        for (int r = 0; r < NMAT; r++) {
            const uint32_t stg = sb + B_OFF + (uint32_t)(r & 1) * B_STAGE;

            if (r + 1 < NMAT) {
                const uint32_t nstg = sb + B_OFF + (uint32_t)((r + 1) & 1) * B_STAGE;
                #pragma unroll
                for (int i = 0; i < 8; i++) {
                    const int q  = tid + i * 256;
                    const int n  = q >> 4;
                    const int ch = q & 15;
                    const __half* src = g_wfh + (size_t)(r + 1) * FEAT * FEAT
                                      + n * FEAT + ch * 8;
                    const uint32_t dst = nstg + (uint32_t)n * APITCH + (uint32_t)ch * 16u;
                    CP_ASYNC16(dst, src);
                }
                CP_COMMIT();
                asm volatile("cp.async.wait_group 1;" ::: "memory");
            } else {
                asm volatile("cp.async.wait_group 0;" ::: "memory");
            }
            __syncthreads();   // B(r) + A visible to all

            float acc[4][4][4];
            #pragma unroll
            for (int i = 0; i < 4; i++)
                #pragma unroll
                for (int j = 0; j < 4; j++)
                    #pragma unroll
                    for (int q = 0; q < 4; q++) acc[i][j][q] = 0.f;

            const uint32_t aHi = sb + A_HI_OFF + (uint32_t)(m_warp * APITCH) + a_off;
            const uint32_t aLo = sb + A_LO_OFF + (uint32_t)(m_warp * APITCH) + a_off;
            const uint32_t bHi = stg + (uint32_t)(n_warp * APITCH) + b_off;

            #pragma unroll
            for (int ks = 0; ks < 8; ks++) {
                const uint32_t kb = (uint32_t)(ks * 32);
                uint32_t ah[4][4], al[4][4], bh[2][4];
                #pragma unroll
                for (int i = 0; i < 4; i++) {
                    LDSM4(ah[i][0], ah[i][1], ah[i][2], ah[i][3],
                          aHi + (uint32_t)(i * 16 * APITCH) + kb);
                    LDSM4(al[i][0], al[i][1], al[i][2], al[i][3],
                          aLo + (uint32_t)(i * 16 * APITCH) + kb);
                }
                #pragma unroll
                for (int j2 = 0; j2 < 2; j2++) {
                    LDSM4(bh[j2][0], bh[j2][1], bh[j2][2], bh[j2][3],
                          bHi + (uint32_t)(j2 * 16 * APITCH) + kb);
                }
                #pragma unroll
                for (int i = 0; i < 4; i++) {
                    #pragma unroll
                    for (int j = 0; j < 4; j++) {
                        const int j2 = j >> 1, jj = (j & 1) * 2;
                        MMA_F16(acc[i][j], ah[i], bh[j2][jj], bh[j2][jj + 1]);
                        MMA_F16(acc[i][j], al[i], bh[j2][jj], bh[j2][jj + 1]);
                    }
                }
            }

            // ---- epilogue ----
            if (r < NREL) {
                __half* __restrict__ C = g_all_h + (size_t)r * N_NODES * FEAT;
                #pragma unroll
                for (int i = 0; i < 4; i++) {
                    const int row0 = m0 + m_warp + i * 16 + (lane >> 2);
                    #pragma unroll
                    for (int j = 0; j < 4; j++) {
                        const int c = n_warp + j * 8 + (lane & 3) * 2;
                        if (row0 < N_NODES)
                            *reinterpret_cast<__half2*>(C + (size_t)row0 * FEAT + c) =
                                __floats2half2_rn(acc[i][j][0], acc[i][j][1]);
                        if (row0 + 8 < N_NODES)
                            *reinterpret_cast<__half2*>(C + (size_t)(row0 + 8) * FEAT + c) =
                                __floats2half2_rn(acc[i][j][2], acc[i][j][3]);
                    }
                }
            } else {
                float* __restrict__ C = out;
                #pragma unroll
                for (int i = 0; i < 4; i++) {
                    const int row0 = m0 + m_warp + i * 16 + (lane >> 2);
                    #pragma unroll
                    for (int j = 0; j < 4; j++) {
                        const int c = n_warp + j * 8 + (lane & 3) * 2;
                        if (row0 < N_NODES)
                            *reinterpret_cast<float2*>(C + (size_t)row0 * FEAT + c) =
                                make_float2(acc[i][j][0], acc[i][j][1]);
                        if (row0 + 8 < N_NODES)
                            *reinterpret_cast<float2*>(C + (size_t)(row0 + 8) * FEAT + c) =
                                make_float2(acc[i][j][2], acc[i][j][3]);
                    }
                }
            }
            __syncthreads();   // protect B stage / A buffer about to be reused
        }
    }
}

// ============================================================================
// CSR-by-dst build (parallel 3-phase scan)
// ============================================================================
__global__ void hist_kernel(const int* __restrict__ dst) {
    const int e = blockIdx.x * blockDim.x + threadIdx.x;
    if (e < N_EDGES) atomicAdd(&g_count[dst[e]], 1);
}

#define SCAN_NB 196   // ceil(100000/512)

__global__ __launch_bounds__(512) void scan1_kernel() {
    __shared__ int sh[512];
    const int i = blockIdx.x * 512 + threadIdx.x;
    sh[threadIdx.x] = (i < N_NODES) ? g_count[i] : 0;
    __syncthreads();
    for (int off = 256; off > 0; off >>= 1) {
        if (threadIdx.x < off) sh[threadIdx.x] += sh[threadIdx.x + off];
        __syncthreads();
    }
    if (threadIdx.x == 0) g_bsum[blockIdx.x] = sh[0];
}

__global__ __launch_bounds__(256) void scan2_kernel() {
    __shared__ int sh[256];
    const int t = threadIdx.x;
    const int v = (t < SCAN_NB) ? g_bsum[t] : 0;
    sh[t] = v;
    __syncthreads();
    for (int off = 1; off < 256; off <<= 1) {
        int x = (t >= off) ? sh[t - off] : 0;
        __syncthreads();
        sh[t] += x;
        __syncthreads();
    }
    if (t < SCAN_NB) g_boff[t] = sh[t] - v;
    if (t == 255) g_start[N_NODES] = sh[255];
}

__global__ __launch_bounds__(512) void scan3_kernel() {
    __shared__ int sh[512];
    const int i = blockIdx.x * 512 + threadIdx.x;
    const int v = (i < N_NODES) ? g_count[i] : 0;
    sh[threadIdx.x] = v;
    __syncthreads();
    for (int off = 1; off < 512; off <<= 1) {
        int x = (threadIdx.x >= off) ? sh[threadIdx.x - off] : 0;
        __syncthreads();
        sh[threadIdx.x] += x;
        __syncthreads();
    }
    if (i < N_NODES) g_start[i] = g_boff[blockIdx.x] + sh[threadIdx.x] - v;
}

__global__ void scatter_kernel(const int* __restrict__ dst,
                               const int* __restrict__ src,
                               const int* __restrict__ eid,
                               const float* __restrict__ norm) {
    const int e = blockIdx.x * blockDim.x + threadIdx.x;
    if (e < N_EDGES) {
        const int d = dst[e];
        const int pos = g_start[d] + atomicAdd(&g_cursor[d], 1);
        g_row[pos] = eid[e] * N_NODES + src[e];
        g_nrm[pos] = norm[e];
    }
}

// ============================================================================
// Gather-reduce + fused relu epilogue (one warp per dst node), fp16 gathers
// ============================================================================
__global__ __launch_bounds__(256) void reduce_kernel(float* __restrict__ out)
{
    const int w    = (blockIdx.x * blockDim.x + threadIdx.x) >> 5;
    const int lane = threadIdx.x & 31;
    if (w >= N_NODES) return;

    int i = g_start[w];
    const int end = g_start[w + 1];
    float4 acc = make_float4(0.f, 0.f, 0.f, 0.f);

    if (i < end) {
        int   r0 = g_row[i];
        float n0 = g_nrm[i];
        #pragma unroll 2
        for (; i + 1 < end; i++) {
            const int   r1 = g_row[i + 1];
            const float n1 = g_nrm[i + 1];
            const uint2 u = reinterpret_cast<const uint2*>(
                g_all_h + (size_t)r0 * FEAT)[lane];
            const float2 v0 = __half22float2(*reinterpret_cast<const __half2*>(&u.x));
            const float2 v1 = __half22float2(*reinterpret_cast<const __half2*>(&u.y));
            acc.x = fmaf(v0.x, n0, acc.x);
            acc.y = fmaf(v0.y, n0, acc.y);
            acc.z = fmaf(v1.x, n0, acc.z);
            acc.w = fmaf(v1.y, n0, acc.w);
            r0 = r1; n0 = n1;
        }
        const uint2 u = reinterpret_cast<const uint2*>(
            g_all_h + (size_t)r0 * FEAT)[lane];
        const float2 v0 = __half22float2(*reinterpret_cast<const __half2*>(&u.x));
        const float2 v1 = __half22float2(*reinterpret_cast<const __half2*>(&u.y));
        acc.x = fmaf(v0.x, n0, acc.x);
        acc.y = fmaf(v0.y, n0, acc.y);
        acc.z = fmaf(v1.x, n0, acc.z);
        acc.w = fmaf(v1.y, n0, acc.w);
    }

    float4* op = reinterpret_cast<float4*>(out + (size_t)w * FEAT) + lane;
    float4 base = *op;   // h @ W0
    base.x = fmaxf(base.x + acc.x, 0.f);
    base.y = fmaxf(base.y + acc.y, 0.f);
    base.z = fmaxf(base.z + acc.z, 0.f);
    base.w = fmaxf(base.w + acc.w, 0.f);
    *op = base;
}

// ============================================================================
extern "C" void kernel_launch(void* const* d_in, const int* in_sizes, int n_in,
                              void* d_out, int out_size)
{
    const float* h      = (const float*)d_in[0];
    const float* weight = (const float*)d_in[1];
    const float* W0     = (const float*)d_in[2];
    const float* norm   = (const float*)d_in[3];
    const int*   src    = (const int*)d_in[4];
    const int*   dst    = (const int*)d_in[5];
    const int*   eid    = (const int*)d_in[6];
    float* out = (float*)d_out;
    (void)in_sizes; (void)n_in; (void)out_size;

    cudaFuncSetAttribute(gemm_mma_kernel,
                         cudaFuncAttributeMaxDynamicSharedMemorySize, SMEM_BYTES);

    // Side stream + events, created once on the (uncaptured) correctness call.
    static cudaStream_t s2 = nullptr;
    static cudaEvent_t  evFork = nullptr, evJoin = nullptr;
    if (s2 == nullptr) {
        if (cudaStreamCreateWithFlags(&s2, cudaStreamNonBlocking) != cudaSuccess)
            s2 = nullptr;
        if (s2) {
            cudaEventCreateWithFlags(&evFork, cudaEventDisableTiming);
            cudaEventCreateWithFlags(&evJoin, cudaEventDisableTiming);
        }
    }

    init_kernel<<<NMAT + ZERO_BLOCKS, 256>>>(weight, W0);

    if (s2) {
        cudaEventRecord(evFork, 0);
        cudaStreamWaitEvent(s2, evFork, 0);

        // main stream: the big GEMM
        gemm_mma_kernel<<<GEMM_GRID, 256, SMEM_BYTES>>>(h, out);

        // side stream: CSR prep chain (disjoint buffers from the GEMM)
        hist_kernel<<<(N_EDGES + 255) / 256, 256, 0, s2>>>(dst);
        scan1_kernel<<<SCAN_NB, 512, 0, s2>>>();
        scan2_kernel<<<1, 256, 0, s2>>>();
        scan3_kernel<<<SCAN_NB, 512, 0, s2>>>();
        scatter_kernel<<<(N_EDGES + 255) / 256, 256, 0, s2>>>(dst, src, eid, norm);

        cudaEventRecord(evJoin, s2);
        cudaStreamWaitEvent(0, evJoin, 0);
    } else {
        // fallback: sequential
        hist_kernel<<<(N_EDGES + 255) / 256, 256>>>(dst);
        scan1_kernel<<<SCAN_NB, 512>>>();
        scan2_kernel<<<1, 256>>>();
        scan3_kernel<<<SCAN_NB, 512>>>();
        gemm_mma_kernel<<<GEMM_GRID, 256, SMEM_BYTES>>>(h, out);
        scatter_kernel<<<(N_EDGES + 255) / 256, 256>>>(dst, src, eid, norm);
    }

    reduce_kernel<<<(N_NODES * 32 + 255) / 256, 256>>>(out);
}

// round 7
// speedup vs baseline: 3.7736x; 1.1896x over previous
#include <cuda_runtime.h>
#include <cuda_fp16.h>
#include <cstdint>
#include <cstddef>

#define N_NODES 100000
#define N_EDGES 600000
#define FEAT    128
#define NREL    5
#define NMAT    6          // 5 relations + W0
#define NTILES  ((N_NODES + 127) / 128)   // 782
#define GEMM_GRID 296      // 2 CTAs / SM

// ---------------- device-global scratch (allocation-free contract) ---------
__device__ __half g_all_h[(size_t)NREL * N_NODES * FEAT];           // 128 MB, fp16
__device__ __half g_wfh[NMAT * FEAT * FEAT];                        // W^T fp16, [r][n][k]
__device__ int   g_count[N_NODES];
__device__ int   g_cursor[N_NODES];
__device__ int   g_start[N_NODES + 1];
__device__ int   g_row[N_EDGES];     // packed: eid*N_NODES + src, sorted by dst
__device__ float g_nrm[N_EDGES];     // norm, sorted by dst
__device__ int   g_bsum[256];
__device__ int   g_boff[256];

// ---------------- helpers ----------------------------------------------------
static __device__ __forceinline__ uint32_t smem_u32(const void* p) {
    uint32_t a;
    asm("{ .reg .u64 t; cvta.to.shared.u64 t, %1; cvt.u32.u64 %0, t; }"
        : "=r"(a) : "l"(p));
    return a;
}

#define LDSM4(r0, r1, r2, r3, a)                                              \
    asm volatile("ldmatrix.sync.aligned.m8n8.x4.shared.b16 {%0,%1,%2,%3}, [%4];" \
                 : "=r"(r0), "=r"(r1), "=r"(r2), "=r"(r3) : "r"(a))

#define MMA_F16(d, a, bb0, bb1)                                               \
    asm volatile("mma.sync.aligned.m16n8k16.row.col.f32.f16.f16.f32 "         \
                 "{%0,%1,%2,%3}, {%4,%5,%6,%7}, {%8,%9}, {%0,%1,%2,%3};"      \
                 : "+f"((d)[0]), "+f"((d)[1]), "+f"((d)[2]), "+f"((d)[3])     \
                 : "r"((a)[0]), "r"((a)[1]), "r"((a)[2]), "r"((a)[3]),        \
                   "r"(bb0), "r"(bb1))

#define CP_ASYNC16(dst, src)                                                  \
    asm volatile("cp.async.cg.shared.global [%0], [%1], 16;"                  \
                 :: "r"(dst), "l"(src) : "memory")
#define CP_COMMIT() asm volatile("cp.async.commit_group;" ::: "memory")

// ---------------- SMEM layout (bytes) ----------------------------------------
// padded row pitch: 136 fp16 = 272 B (bank-rotation 4 -> conflict-free ldmatrix)
#define APITCH   272u
#define A_OFF    0u              // 128 rows x 272 B = 34816
#define B_OFF    34816u          // 2 stages x 34816
#define B_STAGE  34816u
#define SMEM_BYTES 104448u       // fits 2 CTAs / SM (208896 <= ~228KB)

// ============================================================================
// Fused init: blocks 0..5 transpose weights to fp16; the rest zero counters.
// ============================================================================
#define ZERO_BLOCKS ((N_NODES + 255) / 256)
__global__ void init_kernel(const float* __restrict__ weight,
                            const float* __restrict__ W0)
{
    if (blockIdx.x < NMAT) {
        const int r = blockIdx.x;
        const float* src = (r < NREL) ? (weight + (size_t)r * FEAT * FEAT) : W0;
        for (int i = threadIdx.x; i < FEAT * FEAT; i += blockDim.x) {
            const int k = i >> 7, n = i & 127;
            g_wfh[r * FEAT * FEAT + n * FEAT + k] = __float2half_rn(src[k * FEAT + n]);
        }
    } else {
        const int i = (blockIdx.x - NMAT) * blockDim.x + threadIdx.x;
        if (i < N_NODES) { g_count[i] = 0; g_cursor[i] = 0; }
    }
}

// ============================================================================
// Persistent mma.sync fp16 GEMM, occupancy 2: 296 CTAs over 782 tiles x 6 rel.
// D = A * B (single fp16 term, fp32 accumulate)
// r<5 -> g_all_h (fp16), r==5 -> out (fp32, h@W0)
// ============================================================================
__global__ __launch_bounds__(256, 2)
void gemm_mma_kernel(const float* __restrict__ h, float* __restrict__ out)
{
    extern __shared__ __align__(1024) char smem[];
    const uint32_t sb  = smem_u32(smem);
    const int tid  = threadIdx.x;
    const int lane = tid & 31;
    const int warp = tid >> 5;
    const int wm   = warp & 1;          // m half (0/1)
    const int wn   = warp >> 1;         // n quarter (0..3)
    const int m_warp = wm * 64;
    const int n_warp = wn * 32;

    const uint32_t a_off = (uint32_t)((((lane >> 3) & 1) * 8 + (lane & 7)) * APITCH
                                      + (lane >> 4) * 16);
    const uint32_t b_off = (uint32_t)((((lane >> 4) * 8) + (lane & 7)) * APITCH
                                      + ((lane >> 3) & 1) * 16);

    #pragma unroll 1
    for (int tile = blockIdx.x; tile < NTILES; tile += GEMM_GRID) {
        const int m0 = tile * 128;

        // ---- cp.async B(relation 0) into stage 0 (overlaps A load) ----
        #pragma unroll
        for (int i = 0; i < 8; i++) {
            const int q  = tid + i * 256;       // 2048 chunks of 16B
            const int n  = q >> 4;
            const int ch = q & 15;
            const __half* src = g_wfh + n * FEAT + ch * 8;
            const uint32_t dst = sb + B_OFF + (uint32_t)n * APITCH + (uint32_t)ch * 16u;
            CP_ASYNC16(dst, src);
        }
        CP_COMMIT();

        // ---- load A tile as fp16 (resident across relations) ----
        #pragma unroll
        for (int i = 0; i < 16; i++) {
            const int q   = tid + i * 256;      // 4096 float4s
            const int row = q >> 5;
            const int f4  = q & 31;
            const int gm  = m0 + row;
            float4 v = make_float4(0.f, 0.f, 0.f, 0.f);
            if (gm < N_NODES)
                v = *reinterpret_cast<const float4*>(h + (size_t)gm * FEAT + f4 * 4);
            const __half2 h0 = __floats2half2_rn(v.x, v.y);
            const __half2 h1 = __floats2half2_rn(v.z, v.w);
            const uint32_t d = (uint32_t)(row * APITCH + f4 * 8);
            *reinterpret_cast<__half2*>(smem + A_OFF + d)     = h0;
            *reinterpret_cast<__half2*>(smem + A_OFF + d + 4) = h1;
        }

        // ---- relation loop ----
        #pragma unroll 1
        for (int r = 0; r < NMAT; r++) {
            const uint32_t stg = sb + B_OFF + (uint32_t)(r & 1) * B_STAGE;

            if (r + 1 < NMAT) {
                const uint32_t nstg = sb + B_OFF + (uint32_t)((r + 1) & 1) * B_STAGE;
                #pragma unroll
                for (int i = 0; i < 8; i++) {
                    const int q  = tid + i * 256;
                    const int n  = q >> 4;
                    const int ch = q & 15;
                    const __half* src = g_wfh + (size_t)(r + 1) * FEAT * FEAT
                                      + n * FEAT + ch * 8;
                    const uint32_t dst = nstg + (uint32_t)n * APITCH + (uint32_t)ch * 16u;
                    CP_ASYNC16(dst, src);
                }
                CP_COMMIT();
                asm volatile("cp.async.wait_group 1;" ::: "memory");
            } else {
                asm volatile("cp.async.wait_group 0;" ::: "memory");
            }
            __syncthreads();   // B(r) + A visible to all

            float acc[4][4][4];
            #pragma unroll
            for (int i = 0; i < 4; i++)
                #pragma unroll
                for (int j = 0; j < 4; j++)
                    #pragma unroll
                    for (int q = 0; q < 4; q++) acc[i][j][q] = 0.f;

            const uint32_t aBase = sb + A_OFF + (uint32_t)(m_warp * APITCH) + a_off;
            const uint32_t bBase = stg + (uint32_t)(n_warp * APITCH) + b_off;

            #pragma unroll
            for (int ks = 0; ks < 8; ks++) {
                const uint32_t kb = (uint32_t)(ks * 32);
                uint32_t ah[4][4], bh[2][4];
                #pragma unroll
                for (int i = 0; i < 4; i++) {
                    LDSM4(ah[i][0], ah[i][1], ah[i][2], ah[i][3],
                          aBase + (uint32_t)(i * 16 * APITCH) + kb);
                }
                #pragma unroll
                for (int j2 = 0; j2 < 2; j2++) {
                    LDSM4(bh[j2][0], bh[j2][1], bh[j2][2], bh[j2][3],
                          bBase + (uint32_t)(j2 * 16 * APITCH) + kb);
                }
                #pragma unroll
                for (int i = 0; i < 4; i++) {
                    #pragma unroll
                    for (int j = 0; j < 4; j++) {
                        const int j2 = j >> 1, jj = (j & 1) * 2;
                        MMA_F16(acc[i][j], ah[i], bh[j2][jj], bh[j2][jj + 1]);
                    }
                }
            }

            // ---- epilogue ----
            if (r < NREL) {
                __half* __restrict__ C = g_all_h + (size_t)r * N_NODES * FEAT;
                #pragma unroll
                for (int i = 0; i < 4; i++) {
                    const int row0 = m0 + m_warp + i * 16 + (lane >> 2);
                    #pragma unroll
                    for (int j = 0; j < 4; j++) {
                        const int c = n_warp + j * 8 + (lane & 3) * 2;
                        if (row0 < N_NODES)
                            *reinterpret_cast<__half2*>(C + (size_t)row0 * FEAT + c) =
                                __floats2half2_rn(acc[i][j][0], acc[i][j][1]);
                        if (row0 + 8 < N_NODES)
                            *reinterpret_cast<__half2*>(C + (size_t)(row0 + 8) * FEAT + c) =
                                __floats2half2_rn(acc[i][j][2], acc[i][j][3]);
                    }
                }
            } else {
                float* __restrict__ C = out;
                #pragma unroll
                for (int i = 0; i < 4; i++) {
                    const int row0 = m0 + m_warp + i * 16 + (lane >> 2);
                    #pragma unroll
                    for (int j = 0; j < 4; j++) {
                        const int c = n_warp + j * 8 + (lane & 3) * 2;
                        if (row0 < N_NODES)
                            *reinterpret_cast<float2*>(C + (size_t)row0 * FEAT + c) =
                                make_float2(acc[i][j][0], acc[i][j][1]);
                        if (row0 + 8 < N_NODES)
                            *reinterpret_cast<float2*>(C + (size_t)(row0 + 8) * FEAT + c) =
                                make_float2(acc[i][j][2], acc[i][j][3]);
                    }
                }
            }
            __syncthreads();   // protect B stage / A buffer about to be reused
        }
    }
}

// ============================================================================
// CSR-by-dst build (parallel 3-phase scan)
// ============================================================================
__global__ void hist_kernel(const int* __restrict__ dst) {
    const int e = blockIdx.x * blockDim.x + threadIdx.x;
    if (e < N_EDGES) atomicAdd(&g_count[dst[e]], 1);
}

#define SCAN_NB 196   // ceil(100000/512)

__global__ __launch_bounds__(512) void scan1_kernel() {
    __shared__ int sh[512];
    const int i = blockIdx.x * 512 + threadIdx.x;
    sh[threadIdx.x] = (i < N_NODES) ? g_count[i] : 0;
    __syncthreads();
    for (int off = 256; off > 0; off >>= 1) {
        if (threadIdx.x < off) sh[threadIdx.x] += sh[threadIdx.x + off];
        __syncthreads();
    }
    if (threadIdx.x == 0) g_bsum[blockIdx.x] = sh[0];
}

__global__ __launch_bounds__(256) void scan2_kernel() {
    __shared__ int sh[256];
    const int t = threadIdx.x;
    const int v = (t < SCAN_NB) ? g_bsum[t] : 0;
    sh[t] = v;
    __syncthreads();
    for (int off = 1; off < 256; off <<= 1) {
        int x = (t >= off) ? sh[t - off] : 0;
        __syncthreads();
        sh[t] += x;
        __syncthreads();
    }
    if (t < SCAN_NB) g_boff[t] = sh[t] - v;
    if (t == 255) g_start[N_NODES] = sh[255];
}

__global__ __launch_bounds__(512) void scan3_kernel() {
    __shared__ int sh[512];
    const int i = blockIdx.x * 512 + threadIdx.x;
    const int v = (i < N_NODES) ? g_count[i] : 0;
    sh[threadIdx.x] = v;
    __syncthreads();
    for (int off = 1; off < 512; off <<= 1) {
        int x = (threadIdx.x >= off) ? sh[threadIdx.x - off] : 0;
        __syncthreads();
        sh[threadIdx.x] += x;
        __syncthreads();
    }
    if (i < N_NODES) g_start[i] = g_boff[blockIdx.x] + sh[threadIdx.x] - v;
}

__global__ void scatter_kernel(const int* __restrict__ dst,
                               const int* __restrict__ src,
                               const int* __restrict__ eid,
                               const float* __restrict__ norm) {
    const int e = blockIdx.x * blockDim.x + threadIdx.x;
    if (e < N_EDGES) {
        const int d = dst[e];
        const int pos = g_start[d] + atomicAdd(&g_cursor[d], 1);
        g_row[pos] = eid[e] * N_NODES + src[e];
        g_nrm[pos] = norm[e];
    }
}

// ============================================================================
// Gather-reduce + fused relu epilogue (one warp per dst node), fp16 gathers
// ============================================================================
__global__ __launch_bounds__(256) void reduce_kernel(float* __restrict__ out)
{
    const int w    = (blockIdx.x * blockDim.x + threadIdx.x) >> 5;
    const int lane = threadIdx.x & 31;
    if (w >= N_NODES) return;

    int i = g_start[w];
    const int end = g_start[w + 1];
    float4 acc = make_float4(0.f, 0.f, 0.f, 0.f);

    if (i < end) {
        int   r0 = g_row[i];
        float n0 = g_nrm[i];
        #pragma unroll 2
        for (; i + 1 < end; i++) {
            const int   r1 = g_row[i + 1];
            const float n1 = g_nrm[i + 1];
            const uint2 u = reinterpret_cast<const uint2*>(
                g_all_h + (size_t)r0 * FEAT)[lane];
            const float2 v0 = __half22float2(*reinterpret_cast<const __half2*>(&u.x));
            const float2 v1 = __half22float2(*reinterpret_cast<const __half2*>(&u.y));
            acc.x = fmaf(v0.x, n0, acc.x);
            acc.y = fmaf(v0.y, n0, acc.y);
            acc.z = fmaf(v1.x, n0, acc.z);
            acc.w = fmaf(v1.y, n0, acc.w);
            r0 = r1; n0 = n1;
        }
        const uint2 u = reinterpret_cast<const uint2*>(
            g_all_h + (size_t)r0 * FEAT)[lane];
        const float2 v0 = __half22float2(*reinterpret_cast<const __half2*>(&u.x));
        const float2 v1 = __half22float2(*reinterpret_cast<const __half2*>(&u.y));
        acc.x = fmaf(v0.x, n0, acc.x);
        acc.y = fmaf(v0.y, n0, acc.y);
        acc.z = fmaf(v1.x, n0, acc.z);
        acc.w = fmaf(v1.y, n0, acc.w);
    }

    float4* op = reinterpret_cast<float4*>(out + (size_t)w * FEAT) + lane;
    float4 base = *op;   // h @ W0
    base.x = fmaxf(base.x + acc.x, 0.f);
    base.y = fmaxf(base.y + acc.y, 0.f);
    base.z = fmaxf(base.z + acc.z, 0.f);
    base.w = fmaxf(base.w + acc.w, 0.f);
    *op = base;
}

// ============================================================================
extern "C" void kernel_launch(void* const* d_in, const int* in_sizes, int n_in,
                              void* d_out, int out_size)
{
    const float* h      = (const float*)d_in[0];
    const float* weight = (const float*)d_in[1];
    const float* W0     = (const float*)d_in[2];
    const float* norm   = (const float*)d_in[3];
    const int*   src    = (const int*)d_in[4];
    const int*   dst    = (const int*)d_in[5];
    const int*   eid    = (const int*)d_in[6];
    float* out = (float*)d_out;
    (void)in_sizes; (void)n_in; (void)out_size;

    cudaFuncSetAttribute(gemm_mma_kernel,
                         cudaFuncAttributeMaxDynamicSharedMemorySize, SMEM_BYTES);

    // Side stream + events, created once on the (uncaptured) correctness call.
    static cudaStream_t s2 = nullptr;
    static cudaEvent_t  evFork = nullptr, evJoin = nullptr;
    if (s2 == nullptr) {
        if (cudaStreamCreateWithFlags(&s2, cudaStreamNonBlocking) != cudaSuccess)
            s2 = nullptr;
        if (s2) {
            cudaEventCreateWithFlags(&evFork, cudaEventDisableTiming);
            cudaEventCreateWithFlags(&evJoin, cudaEventDisableTiming);
        }
    }

    init_kernel<<<NMAT + ZERO_BLOCKS, 256>>>(weight, W0);

    if (s2) {
        cudaEventRecord(evFork, 0);
        cudaStreamWaitEvent(s2, evFork, 0);

        // main stream: the big GEMM
        gemm_mma_kernel<<<GEMM_GRID, 256, SMEM_BYTES>>>(h, out);

        // side stream: CSR prep chain (disjoint buffers from the GEMM)
        hist_kernel<<<(N_EDGES + 255) / 256, 256, 0, s2>>>(dst);
        scan1_kernel<<<SCAN_NB, 512, 0, s2>>>();
        scan2_kernel<<<1, 256, 0, s2>>>();
        scan3_kernel<<<SCAN_NB, 512, 0, s2>>>();
        scatter_kernel<<<(N_EDGES + 255) / 256, 256, 0, s2>>>(dst, src, eid, norm);

        cudaEventRecord(evJoin, s2);
        cudaStreamWaitEvent(0, evJoin, 0);
    } else {
        // fallback: sequential
        hist_kernel<<<(N_EDGES + 255) / 256, 256>>>(dst);
        scan1_kernel<<<SCAN_NB, 512>>>();
        scan2_kernel<<<1, 256>>>();
        scan3_kernel<<<SCAN_NB, 512>>>();
        gemm_mma_kernel<<<GEMM_GRID, 256, SMEM_BYTES>>>(h, out);
        scatter_kernel<<<(N_EDGES + 255) / 256, 256>>>(dst, src, eid, norm);
    }

    reduce_kernel<<<(N_NODES * 32 + 255) / 256, 256>>>(out);
}

// round 8
// speedup vs baseline: 3.8161x; 1.0113x over previous
#include <cuda_runtime.h>
#include <cuda_fp16.h>
#include <cstdint>
#include <cstddef>

#define N_NODES 100000
#define N_EDGES 600000
#define FEAT    128
#define NREL    5
#define NMAT    6          // 5 relations + W0
#define NTILES  ((N_NODES + 127) / 128)   // 782
#define GEMM_GRID 296      // 2 CTAs / SM

// ---------------- device-global scratch (allocation-free contract) ---------
__device__ __half g_all_h[(size_t)NREL * N_NODES * FEAT];           // 128 MB, fp16
__device__ __half g_wfh[NMAT * FEAT * FEAT];                        // W^T fp16, [r][n][k]
__device__ int   g_count[N_NODES];
__device__ int   g_cursor[N_NODES];
__device__ int   g_start[N_NODES + 1];
__device__ int   g_row[N_EDGES];     // packed: eid*N_NODES + src, sorted by dst
__device__ float g_nrm[N_EDGES];     // norm, sorted by dst
__device__ int   g_bsum[256];
__device__ int   g_boff[256];

// ---------------- helpers ----------------------------------------------------
static __device__ __forceinline__ uint32_t smem_u32(const void* p) {
    uint32_t a;
    asm("{ .reg .u64 t; cvta.to.shared.u64 t, %1; cvt.u32.u64 %0, t; }"
        : "=r"(a) : "l"(p));
    return a;
}

#define LDSM4(r0, r1, r2, r3, a)                                              \
    asm volatile("ldmatrix.sync.aligned.m8n8.x4.shared.b16 {%0,%1,%2,%3}, [%4];" \
                 : "=r"(r0), "=r"(r1), "=r"(r2), "=r"(r3) : "r"(a))

// fp32 accumulator (used for h@W0 -> out)
#define MMA_F16(d, a, bb0, bb1)                                               \
    asm volatile("mma.sync.aligned.m16n8k16.row.col.f32.f16.f16.f32 "         \
                 "{%0,%1,%2,%3}, {%4,%5,%6,%7}, {%8,%9}, {%0,%1,%2,%3};"      \
                 : "+f"((d)[0]), "+f"((d)[1]), "+f"((d)[2]), "+f"((d)[3])     \
                 : "r"((a)[0]), "r"((a)[1]), "r"((a)[2]), "r"((a)[3]),        \
                   "r"(bb0), "r"(bb1))

// fp16 accumulator (2x rate; used for all_h relations, stored fp16 anyway)
#define MMA_F16ACC(d, a, bb0, bb1)                                            \
    asm volatile("mma.sync.aligned.m16n8k16.row.col.f16.f16.f16.f16 "         \
                 "{%0,%1}, {%2,%3,%4,%5}, {%6,%7}, {%0,%1};"                  \
                 : "+r"((d)[0]), "+r"((d)[1])                                 \
                 : "r"((a)[0]), "r"((a)[1]), "r"((a)[2]), "r"((a)[3]),        \
                   "r"(bb0), "r"(bb1))

#define CP_ASYNC16(dst, src)                                                  \
    asm volatile("cp.async.cg.shared.global [%0], [%1], 16;"                  \
                 :: "r"(dst), "l"(src) : "memory")
#define CP_COMMIT() asm volatile("cp.async.commit_group;" ::: "memory")

// ---------------- SMEM layout (bytes) ----------------------------------------
// padded row pitch: 136 fp16 = 272 B (bank-rotation 4 -> conflict-free ldmatrix)
#define APITCH   272u
#define A_OFF    0u              // 128 rows x 272 B = 34816
#define B_OFF    34816u          // 2 stages x 34816
#define B_STAGE  34816u
#define SMEM_BYTES 104448u       // fits 2 CTAs / SM

// ============================================================================
// Fused init: blocks 0..5 transpose weights to fp16; the rest zero counters.
// ============================================================================
#define ZERO_BLOCKS ((N_NODES + 255) / 256)
__global__ void init_kernel(const float* __restrict__ weight,
                            const float* __restrict__ W0)
{
    if (blockIdx.x < NMAT) {
        const int r = blockIdx.x;
        const float* src = (r < NREL) ? (weight + (size_t)r * FEAT * FEAT) : W0;
        for (int i = threadIdx.x; i < FEAT * FEAT; i += blockDim.x) {
            const int k = i >> 7, n = i & 127;
            g_wfh[r * FEAT * FEAT + n * FEAT + k] = __float2half_rn(src[k * FEAT + n]);
        }
    } else {
        const int i = (blockIdx.x - NMAT) * blockDim.x + threadIdx.x;
        if (i < N_NODES) { g_count[i] = 0; g_cursor[i] = 0; }
    }
}

// ============================================================================
// Persistent mma.sync fp16 GEMM, occupancy 2: 296 CTAs over 782 tiles x 6 rel.
// r<5 : fp16-accumulator HMMA (2x rate)  -> g_all_h (fp16)
// r==5: fp32-accumulator HMMA            -> out (fp32, h@W0)
// ============================================================================
__global__ __launch_bounds__(256, 2)
void gemm_mma_kernel(const float* __restrict__ h, float* __restrict__ out)
{
    extern __shared__ __align__(1024) char smem[];
    const uint32_t sb  = smem_u32(smem);
    const int tid  = threadIdx.x;
    const int lane = tid & 31;
    const int warp = tid >> 5;
    const int wm   = warp & 1;          // m half (0/1)
    const int wn   = warp >> 1;         // n quarter (0..3)
    const int m_warp = wm * 64;
    const int n_warp = wn * 32;

    const uint32_t a_off = (uint32_t)((((lane >> 3) & 1) * 8 + (lane & 7)) * APITCH
                                      + (lane >> 4) * 16);
    const uint32_t b_off = (uint32_t)((((lane >> 4) * 8) + (lane & 7)) * APITCH
                                      + ((lane >> 3) & 1) * 16);

    #pragma unroll 1
    for (int tile = blockIdx.x; tile < NTILES; tile += GEMM_GRID) {
        const int m0 = tile * 128;

        // ---- cp.async B(relation 0) into stage 0 (overlaps A load) ----
        #pragma unroll
        for (int i = 0; i < 8; i++) {
            const int q  = tid + i * 256;       // 2048 chunks of 16B
            const int n  = q >> 4;
            const int ch = q & 15;
            const __half* src = g_wfh + n * FEAT + ch * 8;
            const uint32_t dst = sb + B_OFF + (uint32_t)n * APITCH + (uint32_t)ch * 16u;
            CP_ASYNC16(dst, src);
        }
        CP_COMMIT();

        // ---- load A tile as fp16 (resident across relations) ----
        #pragma unroll
        for (int i = 0; i < 16; i++) {
            const int q   = tid + i * 256;      // 4096 float4s
            const int row = q >> 5;
            const int f4  = q & 31;
            const int gm  = m0 + row;
            float4 v = make_float4(0.f, 0.f, 0.f, 0.f);
            if (gm < N_NODES)
                v = *reinterpret_cast<const float4*>(h + (size_t)gm * FEAT + f4 * 4);
            const __half2 h0 = __floats2half2_rn(v.x, v.y);
            const __half2 h1 = __floats2half2_rn(v.z, v.w);
            const uint32_t d = (uint32_t)(row * APITCH + f4 * 8);
            *reinterpret_cast<__half2*>(smem + A_OFF + d)     = h0;
            *reinterpret_cast<__half2*>(smem + A_OFF + d + 4) = h1;
        }

        // ---- relation loop ----
        #pragma unroll 1
        for (int r = 0; r < NMAT; r++) {
            const uint32_t stg = sb + B_OFF + (uint32_t)(r & 1) * B_STAGE;

            if (r + 1 < NMAT) {
                const uint32_t nstg = sb + B_OFF + (uint32_t)((r + 1) & 1) * B_STAGE;
                #pragma unroll
                for (int i = 0; i < 8; i++) {
                    const int q  = tid + i * 256;
                    const int n  = q >> 4;
                    const int ch = q & 15;
                    const __half* src = g_wfh + (size_t)(r + 1) * FEAT * FEAT
                                      + n * FEAT + ch * 8;
                    const uint32_t dst = nstg + (uint32_t)n * APITCH + (uint32_t)ch * 16u;
                    CP_ASYNC16(dst, src);
                }
                CP_COMMIT();
                asm volatile("cp.async.wait_group 1;" ::: "memory");
            } else {
                asm volatile("cp.async.wait_group 0;" ::: "memory");
            }
            __syncthreads();   // B(r) + A visible to all

            const uint32_t aBase = sb + A_OFF + (uint32_t)(m_warp * APITCH) + a_off;
            const uint32_t bBase = stg + (uint32_t)(n_warp * APITCH) + b_off;

            if (r < NREL) {
                // ---------- fp16-accumulator path (2x MMA rate) ----------
                uint32_t facc[4][4][2];
                #pragma unroll
                for (int i = 0; i < 4; i++)
                    #pragma unroll
                    for (int j = 0; j < 4; j++) { facc[i][j][0] = 0u; facc[i][j][1] = 0u; }

                #pragma unroll
                for (int ks = 0; ks < 8; ks++) {
                    const uint32_t kb = (uint32_t)(ks * 32);
                    uint32_t ah[4][4], bh[2][4];
                    #pragma unroll
                    for (int i = 0; i < 4; i++) {
                        LDSM4(ah[i][0], ah[i][1], ah[i][2], ah[i][3],
                              aBase + (uint32_t)(i * 16 * APITCH) + kb);
                    }
                    #pragma unroll
                    for (int j2 = 0; j2 < 2; j2++) {
                        LDSM4(bh[j2][0], bh[j2][1], bh[j2][2], bh[j2][3],
                              bBase + (uint32_t)(j2 * 16 * APITCH) + kb);
                    }
                    #pragma unroll
                    for (int i = 0; i < 4; i++) {
                        #pragma unroll
                        for (int j = 0; j < 4; j++) {
                            const int j2 = j >> 1, jj = (j & 1) * 2;
                            MMA_F16ACC(facc[i][j], ah[i], bh[j2][jj], bh[j2][jj + 1]);
                        }
                    }
                }

                // epilogue: acc already fp16 pairs -> direct half2 stores
                __half* __restrict__ C = g_all_h + (size_t)r * N_NODES * FEAT;
                #pragma unroll
                for (int i = 0; i < 4; i++) {
                    const int row0 = m0 + m_warp + i * 16 + (lane >> 2);
                    #pragma unroll
                    for (int j = 0; j < 4; j++) {
                        const int c = n_warp + j * 8 + (lane & 3) * 2;
                        if (row0 < N_NODES)
                            *reinterpret_cast<uint32_t*>(C + (size_t)row0 * FEAT + c) =
                                facc[i][j][0];
                        if (row0 + 8 < N_NODES)
                            *reinterpret_cast<uint32_t*>(C + (size_t)(row0 + 8) * FEAT + c) =
                                facc[i][j][1];
                    }
                }
            } else {
                // ---------- fp32-accumulator path (h@W0 -> out) ----------
                float acc[4][4][4];
                #pragma unroll
                for (int i = 0; i < 4; i++)
                    #pragma unroll
                    for (int j = 0; j < 4; j++)
                        #pragma unroll
                        for (int q = 0; q < 4; q++) acc[i][j][q] = 0.f;

                #pragma unroll
                for (int ks = 0; ks < 8; ks++) {
                    const uint32_t kb = (uint32_t)(ks * 32);
                    uint32_t ah[4][4], bh[2][4];
                    #pragma unroll
                    for (int i = 0; i < 4; i++) {
                        LDSM4(ah[i][0], ah[i][1], ah[i][2], ah[i][3],
                              aBase + (uint32_t)(i * 16 * APITCH) + kb);
                    }
                    #pragma unroll
                    for (int j2 = 0; j2 < 2; j2++) {
                        LDSM4(bh[j2][0], bh[j2][1], bh[j2][2], bh[j2][3],
                              bBase + (uint32_t)(j2 * 16 * APITCH) + kb);
                    }
                    #pragma unroll
                    for (int i = 0; i < 4; i++) {
                        #pragma unroll
                        for (int j = 0; j < 4; j++) {
                            const int j2 = j >> 1, jj = (j & 1) * 2;
                            MMA_F16(acc[i][j], ah[i], bh[j2][jj], bh[j2][jj + 1]);
                        }
                    }
                }

                float* __restrict__ C = out;
                #pragma unroll
                for (int i = 0; i < 4; i++) {
                    const int row0 = m0 + m_warp + i * 16 + (lane >> 2);
                    #pragma unroll
                    for (int j = 0; j < 4; j++) {
                        const int c = n_warp + j * 8 + (lane & 3) * 2;
                        if (row0 < N_NODES)
                            *reinterpret_cast<float2*>(C + (size_t)row0 * FEAT + c) =
                                make_float2(acc[i][j][0], acc[i][j][1]);
                        if (row0 + 8 < N_NODES)
                            *reinterpret_cast<float2*>(C + (size_t)(row0 + 8) * FEAT + c) =
                                make_float2(acc[i][j][2], acc[i][j][3]);
                    }
                }
            }
            __syncthreads();   // protect B stage / A buffer about to be reused
        }
    }
}

// ============================================================================
// CSR-by-dst build (parallel 3-phase scan)
// ============================================================================
__global__ void hist_kernel(const int* __restrict__ dst) {
    const int e = blockIdx.x * blockDim.x + threadIdx.x;
    if (e < N_EDGES) atomicAdd(&g_count[dst[e]], 1);
}

#define SCAN_NB 196   // ceil(100000/512)

__global__ __launch_bounds__(512) void scan1_kernel() {
    __shared__ int sh[512];
    const int i = blockIdx.x * 512 + threadIdx.x;
    sh[threadIdx.x] = (i < N_NODES) ? g_count[i] : 0;
    __syncthreads();
    for (int off = 256; off > 0; off >>= 1) {
        if (threadIdx.x < off) sh[threadIdx.x] += sh[threadIdx.x + off];
        __syncthreads();
    }
    if (threadIdx.x == 0) g_bsum[blockIdx.x] = sh[0];
}

__global__ __launch_bounds__(256) void scan2_kernel() {
    __shared__ int sh[256];
    const int t = threadIdx.x;
    const int v = (t < SCAN_NB) ? g_bsum[t] : 0;
    sh[t] = v;
    __syncthreads();
    for (int off = 1; off < 256; off <<= 1) {
        int x = (t >= off) ? sh[t - off] : 0;
        __syncthreads();
        sh[t] += x;
        __syncthreads();
    }
    if (t < SCAN_NB) g_boff[t] = sh[t] - v;
    if (t == 255) g_start[N_NODES] = sh[255];
}

__global__ __launch_bounds__(512) void scan3_kernel() {
    __shared__ int sh[512];
    const int i = blockIdx.x * 512 + threadIdx.x;
    const int v = (i < N_NODES) ? g_count[i] : 0;
    sh[threadIdx.x] = v;
    __syncthreads();
    for (int off = 1; off < 512; off <<= 1) {
        int x = (threadIdx.x >= off) ? sh[threadIdx.x - off] : 0;
        __syncthreads();
        sh[threadIdx.x] += x;
        __syncthreads();
    }
    if (i < N_NODES) g_start[i] = g_boff[blockIdx.x] + sh[threadIdx.x] - v;
}

__global__ void scatter_kernel(const int* __restrict__ dst,
                               const int* __restrict__ src,
                               const int* __restrict__ eid,
                               const float* __restrict__ norm) {
    const int e = blockIdx.x * blockDim.x + threadIdx.x;
    if (e < N_EDGES) {
        const int d = dst[e];
        const int pos = g_start[d] + atomicAdd(&g_cursor[d], 1);
        g_row[pos] = eid[e] * N_NODES + src[e];
        g_nrm[pos] = norm[e];
    }
}

// ============================================================================
// Gather-reduce + fused relu epilogue (one warp per dst node), fp16 gathers
// ============================================================================
__global__ __launch_bounds__(256) void reduce_kernel(float* __restrict__ out)
{
    const int w    = (blockIdx.x * blockDim.x + threadIdx.x) >> 5;
    const int lane = threadIdx.x & 31;
    if (w >= N_NODES) return;

    int i = g_start[w];
    const int end = g_start[w + 1];
    float4 acc = make_float4(0.f, 0.f, 0.f, 0.f);

    if (i < end) {
        int   r0 = g_row[i];
        float n0 = g_nrm[i];
        #pragma unroll 2
        for (; i + 1 < end; i++) {
            const int   r1 = g_row[i + 1];
            const float n1 = g_nrm[i + 1];
            const uint2 u = reinterpret_cast<const uint2*>(
                g_all_h + (size_t)r0 * FEAT)[lane];
            const float2 v0 = __half22float2(*reinterpret_cast<const __half2*>(&u.x));
            const float2 v1 = __half22float2(*reinterpret_cast<const __half2*>(&u.y));
            acc.x = fmaf(v0.x, n0, acc.x);
            acc.y = fmaf(v0.y, n0, acc.y);
            acc.z = fmaf(v1.x, n0, acc.z);
            acc.w = fmaf(v1.y, n0, acc.w);
            r0 = r1; n0 = n1;
        }
        const uint2 u = reinterpret_cast<const uint2*>(
            g_all_h + (size_t)r0 * FEAT)[lane];
        const float2 v0 = __half22float2(*reinterpret_cast<const __half2*>(&u.x));
        const float2 v1 = __half22float2(*reinterpret_cast<const __half2*>(&u.y));
        acc.x = fmaf(v0.x, n0, acc.x);
        acc.y = fmaf(v0.y, n0, acc.y);
        acc.z = fmaf(v1.x, n0, acc.z);
        acc.w = fmaf(v1.y, n0, acc.w);
    }

    float4* op = reinterpret_cast<float4*>(out + (size_t)w * FEAT) + lane;
    float4 base = *op;   // h @ W0
    base.x = fmaxf(base.x + acc.x, 0.f);
    base.y = fmaxf(base.y + acc.y, 0.f);
    base.z = fmaxf(base.z + acc.z, 0.f);
    base.w = fmaxf(base.w + acc.w, 0.f);
    *op = base;
}

// ============================================================================
extern "C" void kernel_launch(void* const* d_in, const int* in_sizes, int n_in,
                              void* d_out, int out_size)
{
    const float* h      = (const float*)d_in[0];
    const float* weight = (const float*)d_in[1];
    const float* W0     = (const float*)d_in[2];
    const float* norm   = (const float*)d_in[3];
    const int*   src    = (const int*)d_in[4];
    const int*   dst    = (const int*)d_in[5];
    const int*   eid    = (const int*)d_in[6];
    float* out = (float*)d_out;
    (void)in_sizes; (void)n_in; (void)out_size;

    cudaFuncSetAttribute(gemm_mma_kernel,
                         cudaFuncAttributeMaxDynamicSharedMemorySize, SMEM_BYTES);

    // Side stream + events, created once on the (uncaptured) correctness call.
    static cudaStream_t s2 = nullptr;
    static cudaEvent_t  evFork = nullptr, evJoin = nullptr;
    if (s2 == nullptr) {
        if (cudaStreamCreateWithFlags(&s2, cudaStreamNonBlocking) != cudaSuccess)
            s2 = nullptr;
        if (s2) {
            cudaEventCreateWithFlags(&evFork, cudaEventDisableTiming);
            cudaEventCreateWithFlags(&evJoin, cudaEventDisableTiming);
        }
    }

    init_kernel<<<NMAT + ZERO_BLOCKS, 256>>>(weight, W0);

    if (s2) {
        cudaEventRecord(evFork, 0);
        cudaStreamWaitEvent(s2, evFork, 0);

        // main stream: the big GEMM
        gemm_mma_kernel<<<GEMM_GRID, 256, SMEM_BYTES>>>(h, out);

        // side stream: CSR prep chain (disjoint buffers from the GEMM)
        hist_kernel<<<(N_EDGES + 255) / 256, 256, 0, s2>>>(dst);
        scan1_kernel<<<SCAN_NB, 512, 0, s2>>>();
        scan2_kernel<<<1, 256, 0, s2>>>();
        scan3_kernel<<<SCAN_NB, 512, 0, s2>>>();
        scatter_kernel<<<(N_EDGES + 255) / 256, 256, 0, s2>>>(dst, src, eid, norm);

        cudaEventRecord(evJoin, s2);
        cudaStreamWaitEvent(0, evJoin, 0);
    } else {
        // fallback: sequential
        hist_kernel<<<(N_EDGES + 255) / 256, 256>>>(dst);
        scan1_kernel<<<SCAN_NB, 512>>>();
        scan2_kernel<<<1, 256>>>();
        scan3_kernel<<<SCAN_NB, 512>>>();
        gemm_mma_kernel<<<GEMM_GRID, 256, SMEM_BYTES>>>(h, out);
        scatter_kernel<<<(N_EDGES + 255) / 256, 256>>>(dst, src, eid, norm);
    }

    reduce_kernel<<<(N_NODES * 32 + 255) / 256, 256>>>(out);
}

// round 10
// speedup vs baseline: 4.1308x; 1.0825x over previous
#include <cuda_runtime.h>
#include <cuda_fp16.h>
#include <cstdint>
#include <cstddef>

#define N_NODES 100000
#define N_EDGES 600000
#define FEAT    128
#define NREL    5
#define NMAT    6          // 5 relations + W0
#define NTILES  ((N_NODES + 127) / 128)   // 782
#define GEMM_GRID 296      // 2 CTAs / SM

// ---------------- device-global scratch (allocation-free contract) ---------
__device__ __half g_all_h[(size_t)NREL * N_NODES * FEAT];           // 128 MB, fp16
__device__ __half g_wfh[NMAT * FEAT * FEAT];                        // W^T fp16, [r][n][k]
__device__ int   g_count[N_NODES];
__device__ int   g_cursor[N_NODES];
__device__ int   g_start[N_NODES + 1];
__device__ int2  g_pair[N_EDGES];    // (eid*N_NODES+src, bitcast norm), sorted by dst
__device__ int   g_bsum[256];
__device__ int   g_boff[256];

// ---------------- helpers ----------------------------------------------------
static __device__ __forceinline__ uint32_t smem_u32(const void* p) {
    uint32_t a;
    asm("{ .reg .u64 t; cvta.to.shared.u64 t, %1; cvt.u32.u64 %0, t; }"
        : "=r"(a) : "l"(p));
    return a;
}

static __device__ __forceinline__ uint32_t h2_as_u32(__half2 v) {
    uint32_t u;
    memcpy(&u, &v, 4);
    return u;
}

#define LDSM4(r0, r1, r2, r3, a)                                              \
    asm volatile("ldmatrix.sync.aligned.m8n8.x4.shared.b16 {%0,%1,%2,%3}, [%4];" \
                 : "=r"(r0), "=r"(r1), "=r"(r2), "=r"(r3) : "r"(a))

// fp32 accumulator (used for h@W0 -> out)
#define MMA_F16(d, a, bb0, bb1)                                               \
    asm volatile("mma.sync.aligned.m16n8k16.row.col.f32.f16.f16.f32 "         \
                 "{%0,%1,%2,%3}, {%4,%5,%6,%7}, {%8,%9}, {%0,%1,%2,%3};"      \
                 : "+f"((d)[0]), "+f"((d)[1]), "+f"((d)[2]), "+f"((d)[3])     \
                 : "r"((a)[0]), "r"((a)[1]), "r"((a)[2]), "r"((a)[3]),        \
                   "r"(bb0), "r"(bb1))

// fp16 accumulator (2x rate; all_h relations, stored fp16 anyway)
#define MMA_F16ACC(d, a, bb0, bb1)                                            \
    asm volatile("mma.sync.aligned.m16n8k16.row.col.f16.f16.f16.f16 "         \
                 "{%0,%1}, {%2,%3,%4,%5}, {%6,%7}, {%0,%1};"                  \
                 : "+r"((d)[0]), "+r"((d)[1])                                 \
                 : "r"((a)[0]), "r"((a)[1]), "r"((a)[2]), "r"((a)[3]),        \
                   "r"(bb0), "r"(bb1))

#define CP_ASYNC16(dst, src)                                                  \
    asm volatile("cp.async.cg.shared.global [%0], [%1], 16;"                  \
                 :: "r"(dst), "l"(src) : "memory")
#define CP_COMMIT() asm volatile("cp.async.commit_group;" ::: "memory")

#define STS32(addr, v)                                                        \
    asm volatile("st.shared.u32 [%0], %1;" :: "r"(addr), "r"(v) : "memory")
#define LDS128(v, addr)                                                       \
    asm volatile("ld.shared.v4.u32 {%0,%1,%2,%3}, [%4];"                      \
                 : "=r"((v).x), "=r"((v).y), "=r"((v).z), "=r"((v).w) : "r"(addr))

// ---------------- SMEM layout (bytes) ----------------------------------------
// padded row pitch: 136 fp16 = 272 B (bank-rotation 4 -> conflict-free ldmatrix)
#define APITCH   272u
#define A_OFF    0u              // 128 rows x 272 B = 34816
#define B_OFF    34816u          // 2 stages x 34816
#define B_STAGE  34816u
#define EPI_OFF  104448u         // 8 warps x 1280 B (16 rows x pitch 80) = 10240
#define SMEM_BYTES 114688u       // 2 CTAs/SM: 229376 <= carveout

// ============================================================================
// Fused init: blocks 0..5 transpose weights to fp16; the rest zero counters.
// ============================================================================
#define ZERO_BLOCKS ((N_NODES + 255) / 256)
__global__ void init_kernel(const float* __restrict__ weight,
                            const float* __restrict__ W0)
{
    if (blockIdx.x < NMAT) {
        const int r = blockIdx.x;
        const float* src = (r < NREL) ? (weight + (size_t)r * FEAT * FEAT) : W0;
        for (int i = threadIdx.x; i < FEAT * FEAT; i += blockDim.x) {
            const int k = i >> 7, n = i & 127;
            g_wfh[r * FEAT * FEAT + n * FEAT + k] = __float2half_rn(src[k * FEAT + n]);
        }
    } else {
        const int i = (blockIdx.x - NMAT) * blockDim.x + threadIdx.x;
        if (i < N_NODES) { g_count[i] = 0; g_cursor[i] = 0; }
    }
}

// ============================================================================
// Persistent mma.sync fp16 GEMM, occupancy 2: 296 CTAs over 782 tiles x 6 rel.
// r<5 : fp16-accumulator HMMA, pipelined frags, STG.128 epilogue -> g_all_h
// r==5: fp32-accumulator HMMA -> out (fp32, h@W0)
// ============================================================================
__global__ __launch_bounds__(256, 2)
void gemm_mma_kernel(const float* __restrict__ h, float* __restrict__ out)
{
    extern __shared__ __align__(1024) char smem[];
    const uint32_t sb  = smem_u32(smem);
    const int tid  = threadIdx.x;
    const int lane = tid & 31;
    const int warp = tid >> 5;
    const int wm   = warp & 1;          // m half (0/1)
    const int wn   = warp >> 1;         // n quarter (0..3)
    const int m_warp = wm * 64;
    const int n_warp = wn * 32;

    const uint32_t a_off = (uint32_t)((((lane >> 3) & 1) * 8 + (lane & 7)) * APITCH
                                      + (lane >> 4) * 16);
    const uint32_t b_off = (uint32_t)((((lane >> 4) * 8) + (lane & 7)) * APITCH
                                      + ((lane >> 3) & 1) * 16);
    const uint32_t stW = sb + EPI_OFF + (uint32_t)warp * 1280u;

    #pragma unroll 1
    for (int tile = blockIdx.x; tile < NTILES; tile += GEMM_GRID) {
        const int m0 = tile * 128;

        // ---- cp.async B(relation 0) into stage 0 (overlaps A load) ----
        #pragma unroll
        for (int i = 0; i < 8; i++) {
            const int q  = tid + i * 256;       // 2048 chunks of 16B
            const int n  = q >> 4;
            const int ch = q & 15;
            const __half* src = g_wfh + n * FEAT + ch * 8;
            const uint32_t dst = sb + B_OFF + (uint32_t)n * APITCH + (uint32_t)ch * 16u;
            CP_ASYNC16(dst, src);
        }
        CP_COMMIT();

        // ---- load A tile as fp16 (resident across relations) ----
        #pragma unroll
        for (int i = 0; i < 16; i++) {
            const int q   = tid + i * 256;      // 4096 float4s
            const int row = q >> 5;
            const int f4  = q & 31;
            const int gm  = m0 + row;
            float4 v = make_float4(0.f, 0.f, 0.f, 0.f);
            if (gm < N_NODES)
                v = *reinterpret_cast<const float4*>(h + (size_t)gm * FEAT + f4 * 4);
            uint2 pk;
            pk.x = h2_as_u32(__floats2half2_rn(v.x, v.y));
            pk.y = h2_as_u32(__floats2half2_rn(v.z, v.w));
            const uint32_t d = (uint32_t)(row * APITCH + f4 * 8);
            *reinterpret_cast<uint2*>(smem + A_OFF + d) = pk;
        }

        // ---- relation loop ----
        #pragma unroll 1
        for (int r = 0; r < NMAT; r++) {
            const uint32_t stg = sb + B_OFF + (uint32_t)(r & 1) * B_STAGE;

            if (r + 1 < NMAT) {
                const uint32_t nstg = sb + B_OFF + (uint32_t)((r + 1) & 1) * B_STAGE;
                #pragma unroll
                for (int i = 0; i < 8; i++) {
                    const int q  = tid + i * 256;
                    const int n  = q >> 4;
                    const int ch = q & 15;
                    const __half* src = g_wfh + (size_t)(r + 1) * FEAT * FEAT
                                      + n * FEAT + ch * 8;
                    const uint32_t dst = nstg + (uint32_t)n * APITCH + (uint32_t)ch * 16u;
                    CP_ASYNC16(dst, src);
                }
                CP_COMMIT();
                asm volatile("cp.async.wait_group 1;" ::: "memory");
            } else {
                asm volatile("cp.async.wait_group 0;" ::: "memory");
            }
            __syncthreads();   // B(r) + A visible to all

            const uint32_t aBase = sb + A_OFF + (uint32_t)(m_warp * APITCH) + a_off;
            const uint32_t bBase = stg + (uint32_t)(n_warp * APITCH) + b_off;

            if (r < NREL) {
                // ---------- fp16-accumulator path, double-buffered frags ----------
                uint32_t facc[4][4][2];
                #pragma unroll
                for (int i = 0; i < 4; i++)
                    #pragma unroll
                    for (int j = 0; j < 4; j++) { facc[i][j][0] = 0u; facc[i][j][1] = 0u; }

                uint32_t ah[2][4][4], bh[2][2][4];
                #pragma unroll
                for (int i = 0; i < 4; i++)
                    LDSM4(ah[0][i][0], ah[0][i][1], ah[0][i][2], ah[0][i][3],
                          aBase + (uint32_t)(i * 16 * APITCH));
                #pragma unroll
                for (int j2 = 0; j2 < 2; j2++)
                    LDSM4(bh[0][j2][0], bh[0][j2][1], bh[0][j2][2], bh[0][j2][3],
                          bBase + (uint32_t)(j2 * 16 * APITCH));

                #pragma unroll
                for (int ks = 0; ks < 8; ks++) {
                    const int cur = ks & 1, nxt = cur ^ 1;
                    if (ks < 7) {
                        const uint32_t kb = (uint32_t)((ks + 1) * 32);
                        #pragma unroll
                        for (int i = 0; i < 4; i++)
                            LDSM4(ah[nxt][i][0], ah[nxt][i][1], ah[nxt][i][2], ah[nxt][i][3],
                                  aBase + (uint32_t)(i * 16 * APITCH) + kb);
                        #pragma unroll
                        for (int j2 = 0; j2 < 2; j2++)
                            LDSM4(bh[nxt][j2][0], bh[nxt][j2][1], bh[nxt][j2][2], bh[nxt][j2][3],
                                  bBase + (uint32_t)(j2 * 16 * APITCH) + kb);
                    }
                    #pragma unroll
                    for (int i = 0; i < 4; i++) {
                        #pragma unroll
                        for (int j = 0; j < 4; j++) {
                            const int j2 = j >> 1, jj = (j & 1) * 2;
                            MMA_F16ACC(facc[i][j], ah[cur][i], bh[cur][j2][jj], bh[cur][j2][jj + 1]);
                        }
                    }
                }

                // ---- epilogue: per-warp SMEM repack -> STG.128 (full sectors) ----
                __half* __restrict__ C = g_all_h + (size_t)r * N_NODES * FEAT;
                #pragma unroll
                for (int i = 0; i < 4; i++) {
                    #pragma unroll
                    for (int j = 0; j < 4; j++) {
                        const uint32_t a0 = stW + (uint32_t)((lane >> 2) * 80
                                           + j * 16 + (lane & 3) * 4);
                        STS32(a0, facc[i][j][0]);           // rows 0..7
                        STS32(a0 + 640u, facc[i][j][1]);    // rows 8..15
                    }
                    __syncwarp();
                    #pragma unroll
                    for (int p = 0; p < 2; p++) {
                        const uint32_t la = stW + (uint32_t)((p * 8 + (lane >> 2)) * 80
                                           + (lane & 3) * 16);
                        uint4 v;
                        LDS128(v, la);
                        const int rowg = m0 + m_warp + i * 16 + p * 8 + (lane >> 2);
                        if (rowg < N_NODES)
                            *reinterpret_cast<uint4*>(
                                C + (size_t)rowg * FEAT + n_warp + (lane & 3) * 8) = v;
                    }
                    __syncwarp();
                }
            } else {
                // ---------- fp32-accumulator path (h@W0 -> out) ----------
                float acc[4][4][4];
                #pragma unroll
                for (int i = 0; i < 4; i++)
                    #pragma unroll
                    for (int j = 0; j < 4; j++)
                        #pragma unroll
                        for (int q = 0; q < 4; q++) acc[i][j][q] = 0.f;

                #pragma unroll
                for (int ks = 0; ks < 8; ks++) {
                    const uint32_t kb = (uint32_t)(ks * 32);
                    uint32_t ah[4][4], bh[2][4];
                    #pragma unroll
                    for (int i = 0; i < 4; i++) {
                        LDSM4(ah[i][0], ah[i][1], ah[i][2], ah[i][3],
                              aBase + (uint32_t)(i * 16 * APITCH) + kb);
                    }
                    #pragma unroll
                    for (int j2 = 0; j2 < 2; j2++) {
                        LDSM4(bh[j2][0], bh[j2][1], bh[j2][2], bh[j2][3],
                              bBase + (uint32_t)(j2 * 16 * APITCH) + kb);
                    }
                    #pragma unroll
                    for (int i = 0; i < 4; i++) {
                        #pragma unroll
                        for (int j = 0; j < 4; j++) {
                            const int j2 = j >> 1, jj = (j & 1) * 2;
                            MMA_F16(acc[i][j], ah[i], bh[j2][jj], bh[j2][jj + 1]);
                        }
                    }
                }

                float* __restrict__ C = out;
                #pragma unroll
                for (int i = 0; i < 4; i++) {
                    const int row0 = m0 + m_warp + i * 16 + (lane >> 2);
                    #pragma unroll
                    for (int j = 0; j < 4; j++) {
                        const int c = n_warp + j * 8 + (lane & 3) * 2;
                        if (row0 < N_NODES)
                            *reinterpret_cast<float2*>(C + (size_t)row0 * FEAT + c) =
                                make_float2(acc[i][j][0], acc[i][j][1]);
                        if (row0 + 8 < N_NODES)
                            *reinterpret_cast<float2*>(C + (size_t)(row0 + 8) * FEAT + c) =
                                make_float2(acc[i][j][2], acc[i][j][3]);
                    }
                }
            }
            __syncthreads();   // protect B stage / A buffer about to be reused
        }
    }
}

// ============================================================================
// CSR-by-dst build (parallel 3-phase scan)
// ============================================================================
__global__ void hist_kernel(const int* __restrict__ dst) {
    const int e = blockIdx.x * blockDim.x + threadIdx.x;
    if (e < N_EDGES) atomicAdd(&g_count[dst[e]], 1);
}

#define SCAN_NB 196   // ceil(100000/512)

__global__ __launch_bounds__(512) void scan1_kernel() {
    __shared__ int sh[512];
    const int i = blockIdx.x * 512 + threadIdx.x;
    sh[threadIdx.x] = (i < N_NODES) ? g_count[i] : 0;
    __syncthreads();
    for (int off = 256; off > 0; off >>= 1) {
        if (threadIdx.x < off) sh[threadIdx.x] += sh[threadIdx.x + off];
        __syncthreads();
    }
    if (threadIdx.x == 0) g_bsum[blockIdx.x] = sh[0];
}

__global__ __launch_bounds__(256) void scan2_kernel() {
    __shared__ int sh[256];
    const int t = threadIdx.x;
    const int v = (t < SCAN_NB) ? g_bsum[t] : 0;
    sh[t] = v;
    __syncthreads();
    for (int off = 1; off < 256; off <<= 1) {
        int x = (t >= off) ? sh[t - off] : 0;
        __syncthreads();
        sh[t] += x;
        __syncthreads();
    }
    if (t < SCAN_NB) g_boff[t] = sh[t] - v;
    if (t == 255) g_start[N_NODES] = sh[255];
}

__global__ __launch_bounds__(512) void scan3_kernel() {
    __shared__ int sh[512];
    const int i = blockIdx.x * 512 + threadIdx.x;
    const int v = (i < N_NODES) ? g_count[i] : 0;
    sh[threadIdx.x] = v;
    __syncthreads();
    for (int off = 1; off < 512; off <<= 1) {
        int x = (threadIdx.x >= off) ? sh[threadIdx.x - off] : 0;
        __syncthreads();
        sh[threadIdx.x] += x;
        __syncthreads();
    }
    if (i < N_NODES) g_start[i] = g_boff[blockIdx.x] + sh[threadIdx.x] - v;
}

__global__ void scatter_kernel(const int* __restrict__ dst,
                               const int* __restrict__ src,
                               const int* __restrict__ eid,
                               const float* __restrict__ norm) {
    const int e = blockIdx.x * blockDim.x + threadIdx.x;
    if (e < N_EDGES) {
        const int d = dst[e];
        const int pos = g_start[d] + atomicAdd(&g_cursor[d], 1);
        g_pair[pos] = make_int2(eid[e] * N_NODES + src[e], __float_as_int(norm[e]));
    }
}

// ============================================================================
// Gather-reduce + fused relu epilogue (one warp per dst node), fp16 gathers
// ============================================================================
__global__ __launch_bounds__(256) void reduce_kernel(float* __restrict__ out)
{
    const int w    = (blockIdx.x * blockDim.x + threadIdx.x) >> 5;
    const int lane = threadIdx.x & 31;
    if (w >= N_NODES) return;

    int i = g_start[w];
    const int end = g_start[w + 1];
    float4 acc = make_float4(0.f, 0.f, 0.f, 0.f);

    if (i < end) {
        int2 p0 = g_pair[i];
        #pragma unroll 2
        for (; i + 1 < end; i++) {
            const int2 p1 = g_pair[i + 1];
            const float n0 = __int_as_float(p0.y);
            const uint2 u = reinterpret_cast<const uint2*>(
                g_all_h + (size_t)p0.x * FEAT)[lane];
            const float2 v0 = __half22float2(*reinterpret_cast<const __half2*>(&u.x));
            const float2 v1 = __half22float2(*reinterpret_cast<const __half2*>(&u.y));
            acc.x = fmaf(v0.x, n0, acc.x);
            acc.y = fmaf(v0.y, n0, acc.y);
            acc.z = fmaf(v1.x, n0, acc.z);
            acc.w = fmaf(v1.y, n0, acc.w);
            p0 = p1;
        }
        const float n0 = __int_as_float(p0.y);
        const uint2 u = reinterpret_cast<const uint2*>(
            g_all_h + (size_t)p0.x * FEAT)[lane];
        const float2 v0 = __half22float2(*reinterpret_cast<const __half2*>(&u.x));
        const float2 v1 = __half22float2(*reinterpret_cast<const __half2*>(&u.y));
        acc.x = fmaf(v0.x, n0, acc.x);
        acc.y = fmaf(v0.y, n0, acc.y);
        acc.z = fmaf(v1.x, n0, acc.z);
        acc.w = fmaf(v1.y, n0, acc.w);
    }

    float4* op = reinterpret_cast<float4*>(out + (size_t)w * FEAT) + lane;
    float4 base = *op;   // h @ W0
    base.x = fmaxf(base.x + acc.x, 0.f);
    base.y = fmaxf(base.y + acc.y, 0.f);
    base.z = fmaxf(base.z + acc.z, 0.f);
    base.w = fmaxf(base.w + acc.w, 0.f);
    *op = base;
}

// ============================================================================
extern "C" void kernel_launch(void* const* d_in, const int* in_sizes, int n_in,
                              void* d_out, int out_size)
{
    const float* h      = (const float*)d_in[0];
    const float* weight = (const float*)d_in[1];
    const float* W0     = (const float*)d_in[2];
    const float* norm   = (const float*)d_in[3];
    const int*   src    = (const int*)d_in[4];
    const int*   dst    = (const int*)d_in[5];
    const int*   eid    = (const int*)d_in[6];
    float* out = (float*)d_out;
    (void)in_sizes; (void)n_in; (void)out_size;

    cudaFuncSetAttribute(gemm_mma_kernel,
                         cudaFuncAttributeMaxDynamicSharedMemorySize, SMEM_BYTES);

    // Side stream + events, created once on the (uncaptured) correctness call.
    static cudaStream_t s2 = nullptr;
    static cudaEvent_t  evFork = nullptr, evJoin = nullptr;
    if (s2 == nullptr) {
        if (cudaStreamCreateWithFlags(&s2, cudaStreamNonBlocking) != cudaSuccess)
            s2 = nullptr;
        if (s2) {
            cudaEventCreateWithFlags(&evFork, cudaEventDisableTiming);
            cudaEventCreateWithFlags(&evJoin, cudaEventDisableTiming);
        }
    }

    init_kernel<<<NMAT + ZERO_BLOCKS, 256>>>(weight, W0);

    if (s2) {
        cudaEventRecord(evFork, 0);
        cudaStreamWaitEvent(s2, evFork, 0);

        // main stream: the big GEMM
        gemm_mma_kernel<<<GEMM_GRID, 256, SMEM_BYTES>>>(h, out);

        // side stream: CSR prep chain (disjoint buffers from the GEMM)
        hist_kernel<<<(N_EDGES + 255) / 256, 256, 0, s2>>>(dst);
        scan1_kernel<<<SCAN_NB, 512, 0, s2>>>();
        scan2_kernel<<<1, 256, 0, s2>>>();
        scan3_kernel<<<SCAN_NB, 512, 0, s2>>>();
        scatter_kernel<<<(N_EDGES + 255) / 256, 256, 0, s2>>>(dst, src, eid, norm);

        cudaEventRecord(evJoin, s2);
        cudaStreamWaitEvent(0, evJoin, 0);
    } else {
        // fallback: sequential
        hist_kernel<<<(N_EDGES + 255) / 256, 256>>>(dst);
        scan1_kernel<<<SCAN_NB, 512>>>();
        scan2_kernel<<<1, 256>>>();
        scan3_kernel<<<SCAN_NB, 512>>>();
        gemm_mma_kernel<<<GEMM_GRID, 256, SMEM_BYTES>>>(h, out);
        scatter_kernel<<<(N_EDGES + 255) / 256, 256>>>(dst, src, eid, norm);
    }

    reduce_kernel<<<(N_NODES * 32 + 255) / 256, 256>>>(out);
}